// round 3
// baseline (speedup 1.0000x reference)
#include <cuda_runtime.h>
#include <cuda_bf16.h>
#include <math.h>

// LF-MMI loss: CTC numerator forward + dense bigram denominator forward.
//  - Denominator: linear-domain scaled forward. Texp = exp(trans) as bf16
//    pairs in SMEM (128KB), plain FMA matvec per step, renorm every 32 steps.
//    (Dense mixing keeps alpha dynamic range tiny -> linear domain is safe.)
//  - Numerator: LOG-domain CTC forward (unbounded dynamic range; the lattice
//    spread across S=401 states can exceed e^300, which kills any linear
//    scheme with global renormalization).
//  - Per-frame log_softmax shift cancels exactly in num - den -> skipped.

#define CC 256            // number of classes (fixed by dataset)
#define NEGBIG (-1.0e30f)

__device__ float g_num[512];
__device__ float g_den[512];

// Block-wide sum over 256 threads. red must have >= 8 floats.
__device__ __forceinline__ float blk_sum_256(float v, float* red) {
    int tid = threadIdx.x;
#pragma unroll
    for (int o = 16; o > 0; o >>= 1) v += __shfl_xor_sync(0xffffffffu, v, o);
    if ((tid & 31) == 0) red[tid >> 5] = v;
    __syncthreads();
    float s = red[0] + red[1] + red[2] + red[3] + red[4] + red[5] + red[6] + red[7];
    __syncthreads();
    return s;
}

// ---------------------------------------------------------------------------
// Denominator block: one block per batch element. 256 threads.
// ---------------------------------------------------------------------------
__device__ void den_block(unsigned char* smem_raw,
                          const float* __restrict__ logp,
                          const int* __restrict__ in_len_raw,
                          const float* __restrict__ trans,
                          const float* __restrict__ start,
                          int b, int T, int U) {
    int tid = threadIdx.x;
    unsigned int* Tsh = (unsigned int*)smem_raw;          // 256 rows x 128 u32 (bf16 pairs) = 128KB
    float* a_sh = (float*)(smem_raw + 256 * 128 * 4);     // 256
    float* p_sh = a_sh + 256;                              // 256
    float* part = p_sh + 256;                              // 256
    float* red  = part + 256;                              // 8

    // Build Texp in SMEM as bf16 pairs.
    for (int idx = tid; idx < CC * 128; idx += 256) {
        int i = idx >> 7, jj = idx & 127;
        float e0 = __expf(trans[i * CC + 2 * jj]);
        float e1 = __expf(trans[i * CC + 2 * jj + 1]);
        __nv_bfloat162 h2 = __floats2bfloat162_rn(e0, e1);
        Tsh[i * 128 + jj] = *reinterpret_cast<unsigned int*>(&h2);
    }

    int inlen = in_len_raw[b];
    int lowc = 2 * U + 1;
    if (inlen < lowc) inlen = lowc;
    if (inlen > T)    inlen = T;

    const float* lpb = logp + (size_t)b * T * CC;

    // init: alpha0 = exp(start + logp[:,0]), then normalize
    float a0 = __expf(start[tid] + lpb[tid]);
    a_sh[tid] = a0;
    __syncthreads();
    float s0 = blk_sum_256(a0, red);
    float logZ = logf(s0);
    a_sh[tid] = a0 * (1.0f / s0);

    // prefetch row t=1
    float lp_reg = lpb[CC + tid];
    __syncthreads();

    int h  = tid >> 7;      // K half: 0 -> rows [0,128), 1 -> rows [128,256)
    int jj = tid & 127;     // column pair: cols 2jj, 2jj+1
    const float* ap = a_sh + h * 128;
    const unsigned int* Tp = Tsh + h * 128 * 128 + jj;

    for (int t = 1; t < inlen; ++t) {
        float acc0 = 0.f, acc1 = 0.f, acc2 = 0.f, acc3 = 0.f;
#pragma unroll 8
        for (int i = 0; i < 128; i += 4) {
            float4 a4 = *(const float4*)(ap + i);
            unsigned int u0 = Tp[(i + 0) * 128];
            unsigned int u1 = Tp[(i + 1) * 128];
            unsigned int u2 = Tp[(i + 2) * 128];
            unsigned int u3 = Tp[(i + 3) * 128];
            acc0 += a4.x * __uint_as_float(u0 << 16);
            acc1 += a4.x * __uint_as_float(u0 & 0xffff0000u);
            acc2 += a4.y * __uint_as_float(u1 << 16);
            acc3 += a4.y * __uint_as_float(u1 & 0xffff0000u);
            acc0 += a4.z * __uint_as_float(u2 << 16);
            acc1 += a4.z * __uint_as_float(u2 & 0xffff0000u);
            acc2 += a4.w * __uint_as_float(u3 << 16);
            acc3 += a4.w * __uint_as_float(u3 & 0xffff0000u);
        }
        acc0 += acc2;
        acc1 += acc3;

        float pv = __expf(lp_reg);
        if (t + 1 < inlen) lp_reg = lpb[(size_t)(t + 1) * CC + tid];  // prefetch
        p_sh[tid] = pv;
        if (h) { part[2 * jj] = acc0; part[2 * jj + 1] = acc1; }
        __syncthreads();
        if (!h) {
            float n0 = (acc0 + part[2 * jj])     * p_sh[2 * jj];
            float n1 = (acc1 + part[2 * jj + 1]) * p_sh[2 * jj + 1];
            a_sh[2 * jj]     = n0;
            a_sh[2 * jj + 1] = n1;
        }
        __syncthreads();

        if (((t & 31) == 31) || (t == inlen - 1)) {
            float v = a_sh[tid];
            float s = blk_sum_256(v, red);
            a_sh[tid] = v * (1.0f / s);
            logZ += logf(s);
            __syncthreads();
        }
    }
    // after final normalization sum(a) == 1, so den = logZ
    if (tid == 0) g_den[b] = logZ;
}

// ---------------------------------------------------------------------------
// CTC numerator block (LOG domain): one block per batch element. 256 threads.
// ---------------------------------------------------------------------------
__device__ void ctc_block(unsigned char* smem_raw,
                          const float* __restrict__ logp,
                          const int* __restrict__ targets,
                          const int* __restrict__ in_len_raw,
                          const int* __restrict__ tgt_len_raw,
                          int b, int T, int U) {
    int tid = threadIdx.x;
    int S = 2 * U + 1;

    float* A0  = (float*)smem_raw;          // S+6 (2 leading NEG guards)
    float* A1  = A0 + (S + 6);
    int*   lab = (int*)(A1 + (S + 6));      // S
    int*   skp = lab + S;                   // S  (0/1 skip-allowed)
    float* pc  = (float*)(skp + S);         // 256 (raw logp for frame t)

    const int* tg = targets + (size_t)b * U;
    int tlen = tgt_len_raw[b];
    if (tlen < 1) tlen = 1;
    if (tlen > U) tlen = U;
    int inlen = in_len_raw[b];
    int lowc = 2 * U + 1;
    if (inlen < lowc) inlen = lowc;
    if (inlen > T)    inlen = T;

    for (int s = tid; s < S; s += 256) {
        int l = 0;
        if (s & 1) {
            l = tg[s >> 1];
            if (l < 1) l = 1;
            if (l > CC - 1) l = CC - 1;
        }
        lab[s] = l;
    }
    for (int s = tid; s < S + 6; s += 256) { A0[s] = NEGBIG; A1[s] = NEGBIG; }
    __syncthreads();
    for (int s = tid; s < S; s += 256)
        skp[s] = (s >= 2 && (s & 1) && lab[s] != lab[s - 2]) ? 1 : 0;

    const float* lpb = logp + (size_t)b * T * CC;
    if (tid == 0) {
        A0[2 + 0] = lpb[0];
        A0[2 + 1] = lpb[lab[1]];
    }
    // stage raw logp for t=1, prefetch t=2
    pc[tid] = lpb[CC + tid];
    float lp_reg = lpb[2 * (size_t)CC + tid];
    __syncthreads();

    float* cur = A0;
    float* nxt = A1;
    for (int t = 1; t < inlen; ++t) {
        {
            int s = tid;
            float a  = cur[s + 2];
            float a1 = cur[s + 1];
            float a2 = skp[s] ? cur[s] : NEGBIG;
            float m  = fmaxf(fmaxf(a, a1), a2);
            float v  = __expf(a - m) + __expf(a1 - m) + __expf(a2 - m);
            nxt[s + 2] = m + __logf(v) + pc[lab[s]];
        }
        if (tid < S - 256) {
            int s = tid + 256;
            float a  = cur[s + 2];
            float a1 = cur[s + 1];
            float a2 = skp[s] ? cur[s] : NEGBIG;
            float m  = fmaxf(fmaxf(a, a1), a2);
            float v  = __expf(a - m) + __expf(a1 - m) + __expf(a2 - m);
            nxt[s + 2] = m + __logf(v) + pc[lab[s]];
        }
        __syncthreads();   // done reading pc/cur, nxt written
        if (t + 1 < inlen) {
            pc[tid] = lp_reg;
            if (t + 2 < inlen) lp_reg = lpb[(size_t)(t + 2) * CC + tid];
        }
        __syncthreads();   // pc ready for next step
        float* tmp = cur; cur = nxt; nxt = tmp;
    }
    if (tid == 0) {
        int last = 2 * tlen;
        float a  = cur[last + 2];
        float a1 = cur[last + 1];
        float m  = fmaxf(a, a1);
        g_num[b] = m + logf(expf(a - m) + expf(a1 - m));
    }
}

__global__ __launch_bounds__(256, 1)
void lfmmi_kernel(const float* __restrict__ logp,
                  const int* __restrict__ targets,
                  const int* __restrict__ in_len_raw,
                  const int* __restrict__ tgt_len_raw,
                  const float* __restrict__ trans,
                  const float* __restrict__ start,
                  int B, int T, int U) {
    extern __shared__ unsigned char smem_raw[];
    int blk = blockIdx.x;
    if (blk < B) {
        den_block(smem_raw, logp, in_len_raw, trans, start, blk, T, U);
    } else {
        ctc_block(smem_raw, logp, targets, in_len_raw, tgt_len_raw, blk - B, T, U);
    }
}

__global__ void finalize_kernel(float* out, int B) {
    int tid = threadIdx.x;
    float tot = 0.f;
    int cnt = 0;
    for (int b = tid; b < B; b += 32) {
        float v = g_num[b] - g_den[b];
        if (v > 0.5f * NEGBIG) { tot += v; cnt++; }
    }
#pragma unroll
    for (int o = 16; o > 0; o >>= 1) {
        tot += __shfl_xor_sync(0xffffffffu, tot, o);
        cnt += __shfl_xor_sync(0xffffffffu, cnt, o);
    }
    if (tid == 0) {
        int n = (cnt > 0) ? cnt : 1;
        out[0] = -tot / (float)n;
    }
}

extern "C" void kernel_launch(void* const* d_in, const int* in_sizes, int n_in,
                              void* d_out, int out_size) {
    const float* logp   = (const float*)d_in[0];
    const int*   tgts   = (const int*)d_in[1];
    const int*   inl    = (const int*)d_in[2];
    const int*   tgl    = (const int*)d_in[3];
    const float* trans  = (const float*)d_in[4];
    const float* start  = (const float*)d_in[5];

    int B = in_sizes[2];
    int C = in_sizes[5];            // expected 256
    int U = in_sizes[1] / B;
    int T = in_sizes[0] / (B * C);
    int S = 2 * U + 1;

    size_t den_smem = (size_t)256 * 128 * 4 + (256 + 256 + 256 + 16) * 4;
    size_t ctc_smem = (size_t)(2 * (S + 6) + S + S + 256 + 16) * 4;
    size_t smem = den_smem > ctc_smem ? den_smem : ctc_smem;

    cudaFuncSetAttribute(lfmmi_kernel, cudaFuncAttributeMaxDynamicSharedMemorySize,
                         (int)smem);

    lfmmi_kernel<<<2 * B, 256, smem>>>(logp, tgts, inl, tgl, trans, start, B, T, U);
    finalize_kernel<<<1, 32>>>((float*)d_out, B);
}

// round 7
// speedup vs baseline: 3.4007x; 3.4007x over previous
#include <cuda_runtime.h>
#include <cuda_bf16.h>
#include <math.h>

// LF-MMI loss: CTC numerator (log domain) + dense bigram denominator forward.
// Denominator: linear-domain scaled forward, 2-CTA cluster per batch element.
//   Texp column in registers (64 f32x2 pairs/thread), fma.rn.f32x2 MACs.
//   Alpha loads are C++ longlong2 reads (NOT bare asm): rounds 5/6 failed
//   because non-volatile asm loads with loop-invariant address were CSE'd
//   out of the time loop by the compiler (stale alpha every step).
//   Cross-CTA partial exchange: 1KB DSMEM bulk copy, one mbarrier per buffer.
// Numerator: log-domain CTC forward (validated in round 3).

#define CC 256
#define NEGBIG (-1.0e30f)

__device__ float g_num[512];
__device__ float g_den[512];

// den smem byte offsets (dynamic smem)
#define OFF_MBAR 0       // two 8-byte mbarriers (one per buffer)
#define OFF_ASH  16      // 256 floats
#define OFF_PIN  1040    // 2 x 256 floats (incoming partials, double buffered)
#define OFF_POUT 3088    // 2 x 256 floats (outgoing staging, double buffered)
#define OFF_RED  5136    // 8 floats
#define DEN_SMEM 5184

__device__ __forceinline__ float blk_sum_256(float v, float* red) {
    int tid = threadIdx.x;
#pragma unroll
    for (int o = 16; o > 0; o >>= 1) v += __shfl_xor_sync(0xffffffffu, v, o);
    if ((tid & 31) == 0) red[tid >> 5] = v;
    __syncthreads();
    float s = red[0] + red[1] + red[2] + red[3] + red[4] + red[5] + red[6] + red[7];
    __syncthreads();
    return s;
}

__device__ __forceinline__ unsigned long long pack2(float lo, float hi) {
    unsigned long long r;
    asm("mov.b64 %0, {%1, %2};" : "=l"(r) : "r"(__float_as_uint(lo)), "r"(__float_as_uint(hi)));
    return r;
}

__device__ __forceinline__ void mbar_wait_parity(unsigned int mbar, unsigned int parity) {
    asm volatile(
        "{\n\t"
        ".reg .pred P;\n\t"
        "WL_%=:\n\t"
        "mbarrier.try_wait.parity.acquire.cluster.shared::cta.b64 P, [%0], %1, 0x989680;\n\t"
        "@P bra.uni WD_%=;\n\t"
        "bra.uni WL_%=;\n\t"
        "WD_%=:\n\t"
        "}" :: "r"(mbar), "r"(parity) : "memory");
}

// ---------------------------------------------------------------------------
// Denominator: cluster of 2 CTAs per batch element. 256 threads each.
// CTA half h owns source rows [h*128, h*128+128); thread tid owns column tid.
// ---------------------------------------------------------------------------
__device__ void den_block(unsigned char* smem_raw,
                          const float* __restrict__ logp,
                          const int* __restrict__ in_len_raw,
                          const float* __restrict__ trans,
                          const float* __restrict__ start,
                          int b, int h, int T, int U) {
    int tid = threadIdx.x;

    unsigned int sbase;
    asm("{ .reg .u64 t; cvta.to.shared.u64 t, %1; cvt.u32.u64 %0, t; }"
        : "=r"(sbase) : "l"(smem_raw));
    unsigned int mbar_l = sbase + OFF_MBAR;
    unsigned int pout   = sbase + OFF_POUT;

    float* a_sh  = (float*)(smem_raw + OFF_ASH);
    float* p_in  = (float*)(smem_raw + OFF_PIN);
    float* p_out = (float*)(smem_raw + OFF_POUT);
    float* red   = (float*)(smem_raw + OFF_RED);

    int peer = h ^ 1;
    unsigned int mbar_p, pin_p;
    asm("mapa.shared::cluster.u32 %0, %1, %2;" : "=r"(mbar_p) : "r"(mbar_l), "r"(peer));
    asm("mapa.shared::cluster.u32 %0, %1, %2;" : "=r"(pin_p) : "r"(sbase + OFF_PIN), "r"(peer));

    if (tid == 0) {
        asm volatile("mbarrier.init.shared.b64 [%0], %1;" :: "r"(mbar_l),     "r"(1) : "memory");
        asm volatile("mbarrier.init.shared.b64 [%0], %1;" :: "r"(mbar_l + 8), "r"(1) : "memory");
    }

    // This thread's T column in registers: 64 f32x2 pairs (rows pair-major).
    unsigned long long Treg[64];
    const float* trow = trans + (size_t)(h * 128) * CC + tid;
#pragma unroll
    for (int rp = 0; rp < 64; rp++) {
        float e0 = __expf(trow[(2 * rp) * CC]);
        float e1 = __expf(trow[(2 * rp + 1) * CC]);
        Treg[rp] = pack2(e0, e1);
    }

    int inlen = in_len_raw[b];
    int lowc = 2 * U + 1;
    if (inlen < lowc) inlen = lowc;
    if (inlen > T)    inlen = T;

    const float* lpb = logp + (size_t)b * T * CC;

    // alpha0 = exp(start + logp[:,0]) normalized (both CTAs compute identically)
    float a0 = __expf(start[tid] + lpb[tid]);
    __syncthreads();
    float s0 = blk_sum_256(a0, red);
    float logZ = logf(s0);
    a_sh[tid] = a0 * (1.0f / s0);
    float lp_reg = lpb[CC + tid];
    __syncthreads();

    // both CTAs: mbars initialized + alpha ready before any cross-CTA copy
    asm volatile("barrier.cluster.arrive.aligned;" ::: "memory");
    asm volatile("barrier.cluster.wait.aligned;" ::: "memory");

    // C++ vector view of my row-half of alpha (compiler sees aliasing with
    // a_sh stores; __syncthreads() forces reload every iteration).
    const longlong2* ap2 = (const longlong2*)(a_sh + h * 128);

    for (int t = 1; t < inlen; ++t) {
        unsigned long long acc0 = 0ull, acc1 = 0ull, acc2 = 0ull, acc3 = 0ull;
#pragma unroll
        for (int i = 0; i < 16; i++) {
            longlong2 x = ap2[2 * i];        // floats 8i..8i+3 as two f32-pairs
            longlong2 y = ap2[2 * i + 1];    // floats 8i+4..8i+7
            unsigned long long a01 = (unsigned long long)x.x;
            unsigned long long a23 = (unsigned long long)x.y;
            unsigned long long a45 = (unsigned long long)y.x;
            unsigned long long a67 = (unsigned long long)y.y;
            asm("fma.rn.f32x2 %0, %1, %2, %0;" : "+l"(acc0) : "l"(a01), "l"(Treg[4 * i + 0]));
            asm("fma.rn.f32x2 %0, %1, %2, %0;" : "+l"(acc1) : "l"(a23), "l"(Treg[4 * i + 1]));
            asm("fma.rn.f32x2 %0, %1, %2, %0;" : "+l"(acc2) : "l"(a45), "l"(Treg[4 * i + 2]));
            asm("fma.rn.f32x2 %0, %1, %2, %0;" : "+l"(acc3) : "l"(a67), "l"(Treg[4 * i + 3]));
        }
        asm("add.rn.f32x2 %0, %0, %1;" : "+l"(acc0) : "l"(acc1));
        asm("add.rn.f32x2 %0, %0, %1;" : "+l"(acc2) : "l"(acc3));
        asm("add.rn.f32x2 %0, %0, %1;" : "+l"(acc0) : "l"(acc2));
        unsigned int plo, phi;
        asm("mov.b64 {%0, %1}, %2;" : "=r"(plo), "=r"(phi) : "l"(acc0));
        float partial = __uint_as_float(plo) + __uint_as_float(phi);

        int buf = t & 1;
        unsigned int mb_l = mbar_l + (unsigned)buf * 8u;   // my barrier for this buffer
        unsigned int mb_p = mbar_p + (unsigned)buf * 8u;   // peer's barrier for this buffer

        p_out[buf * 256 + tid] = partial;
        __syncthreads();
        if (tid == 0) {
            asm volatile("fence.proxy.async.shared::cta;" ::: "memory");
            asm volatile("mbarrier.arrive.expect_tx.shared.b64 _, [%0], %1;"
                         :: "r"(mb_l), "r"(1024) : "memory");
            asm volatile("cp.async.bulk.shared::cluster.shared::cta.mbarrier::complete_tx::bytes"
                         " [%0], [%1], %2, [%3];"
                         :: "r"(pin_p + (unsigned)buf * 1024u),
                            "r"(pout + (unsigned)buf * 1024u),
                            "r"(1024), "r"(mb_p) : "memory");
        }
        // overlap DSMEM latency with exp + prefetch
        float pv = __expf(lp_reg);
        if (t + 1 < inlen) lp_reg = lpb[(size_t)(t + 1) * CC + tid];

        // mbar[buf] is used at t, t+2, ...: its k-th use has parity k&1, k=(t-1)>>1
        mbar_wait_parity(mb_l, ((unsigned)(t - 1) >> 1) & 1u);
        float an = (partial + p_in[buf * 256 + tid]) * pv;
        a_sh[tid] = an;

        if (((t & 31) == 31) || (t == inlen - 1)) {
            float s = blk_sum_256(an, red);
            a_sh[tid] = an * (1.0f / s);
            logZ += logf(s);
        }
        __syncthreads();
    }
    if (h == 0 && tid == 0) g_den[b] = logZ;

    asm volatile("barrier.cluster.arrive.aligned;" ::: "memory");
    asm volatile("barrier.cluster.wait.aligned;" ::: "memory");
}

// ---------------------------------------------------------------------------
// CTC numerator block (LOG domain): one block per batch element. 256 threads.
// ---------------------------------------------------------------------------
__device__ void ctc_block(unsigned char* smem_raw,
                          const float* __restrict__ logp,
                          const int* __restrict__ targets,
                          const int* __restrict__ in_len_raw,
                          const int* __restrict__ tgt_len_raw,
                          int b, int T, int U) {
    int tid = threadIdx.x;
    int S = 2 * U + 1;

    float* A0  = (float*)smem_raw;          // S+6 (2 leading NEG guards)
    float* A1  = A0 + (S + 6);
    int*   lab = (int*)(A1 + (S + 6));      // S
    int*   skp = lab + S;                   // S
    float* pc  = (float*)(skp + S);         // 256

    const int* tg = targets + (size_t)b * U;
    int tlen = tgt_len_raw[b];
    if (tlen < 1) tlen = 1;
    if (tlen > U) tlen = U;
    int inlen = in_len_raw[b];
    int lowc = 2 * U + 1;
    if (inlen < lowc) inlen = lowc;
    if (inlen > T)    inlen = T;

    for (int s = tid; s < S; s += 256) {
        int l = 0;
        if (s & 1) {
            l = tg[s >> 1];
            if (l < 1) l = 1;
            if (l > CC - 1) l = CC - 1;
        }
        lab[s] = l;
    }
    for (int s = tid; s < S + 6; s += 256) { A0[s] = NEGBIG; A1[s] = NEGBIG; }
    __syncthreads();
    for (int s = tid; s < S; s += 256)
        skp[s] = (s >= 2 && (s & 1) && lab[s] != lab[s - 2]) ? 1 : 0;

    const float* lpb = logp + (size_t)b * T * CC;
    if (tid == 0) {
        A0[2 + 0] = lpb[0];
        A0[2 + 1] = lpb[lab[1]];
    }
    pc[tid] = lpb[CC + tid];
    float lp_reg = lpb[2 * (size_t)CC + tid];
    __syncthreads();

    float* cur = A0;
    float* nxt = A1;
    for (int t = 1; t < inlen; ++t) {
        {
            int s = tid;
            float a  = cur[s + 2];
            float a1 = cur[s + 1];
            float a2 = skp[s] ? cur[s] : NEGBIG;
            float m  = fmaxf(fmaxf(a, a1), a2);
            float v  = __expf(a - m) + __expf(a1 - m) + __expf(a2 - m);
            nxt[s + 2] = m + __logf(v) + pc[lab[s]];
        }
        if (tid < S - 256) {
            int s = tid + 256;
            float a  = cur[s + 2];
            float a1 = cur[s + 1];
            float a2 = skp[s] ? cur[s] : NEGBIG;
            float m  = fmaxf(fmaxf(a, a1), a2);
            float v  = __expf(a - m) + __expf(a1 - m) + __expf(a2 - m);
            nxt[s + 2] = m + __logf(v) + pc[lab[s]];
        }
        __syncthreads();
        if (t + 1 < inlen) {
            pc[tid] = lp_reg;
            if (t + 2 < inlen) lp_reg = lpb[(size_t)(t + 2) * CC + tid];
        }
        __syncthreads();
        float* tmp = cur; cur = nxt; nxt = tmp;
    }
    if (tid == 0) {
        int last = 2 * tlen;
        float a  = cur[last + 2];
        float a1 = cur[last + 1];
        float m  = fmaxf(a, a1);
        g_num[b] = m + logf(expf(a - m) + expf(a1 - m));
    }
}

__global__ __launch_bounds__(256, 1) __cluster_dims__(2, 1, 1)
void lfmmi_kernel(const float* __restrict__ logp,
                  const int* __restrict__ targets,
                  const int* __restrict__ in_len_raw,
                  const int* __restrict__ tgt_len_raw,
                  const float* __restrict__ trans,
                  const float* __restrict__ start,
                  int B, int T, int U) {
    extern __shared__ unsigned char smem_raw[];
    int blk = blockIdx.x;
    if (blk < 2 * B) {
        den_block(smem_raw, logp, in_len_raw, trans, start, blk >> 1, blk & 1, T, U);
    } else if (blk < 3 * B) {
        ctc_block(smem_raw, logp, targets, in_len_raw, tgt_len_raw, blk - 2 * B, T, U);
    }
}

__global__ void finalize_kernel(float* out, int B) {
    int tid = threadIdx.x;
    float tot = 0.f;
    int cnt = 0;
    for (int b = tid; b < B; b += 32) {
        float v = g_num[b] - g_den[b];
        if (v > 0.5f * NEGBIG) { tot += v; cnt++; }
    }
#pragma unroll
    for (int o = 16; o > 0; o >>= 1) {
        tot += __shfl_xor_sync(0xffffffffu, tot, o);
        cnt += __shfl_xor_sync(0xffffffffu, cnt, o);
    }
    if (tid == 0) {
        int n = (cnt > 0) ? cnt : 1;
        out[0] = -tot / (float)n;
    }
}

// pad launches so ncu (-s 5 -c 1) lands on lfmmi_kernel: 5 launches per call
__global__ void dummy_kernel() {}

extern "C" void kernel_launch(void* const* d_in, const int* in_sizes, int n_in,
                              void* d_out, int out_size) {
    const float* logp   = (const float*)d_in[0];
    const int*   tgts   = (const int*)d_in[1];
    const int*   inl    = (const int*)d_in[2];
    const int*   tgl    = (const int*)d_in[3];
    const float* trans  = (const float*)d_in[4];
    const float* start  = (const float*)d_in[5];

    int B = in_sizes[2];
    int C = in_sizes[5];            // expected 256
    int U = in_sizes[1] / B;
    int T = in_sizes[0] / (B * C);
    int S = 2 * U + 1;

    size_t ctc_smem = (size_t)(2 * (S + 6) + 2 * S + 256 + 16) * 4;
    size_t smem = ctc_smem > DEN_SMEM ? ctc_smem : DEN_SMEM;

    int grid = 3 * B;
    if (grid & 1) grid++;           // cluster size 2 divisibility

    lfmmi_kernel<<<grid, 256, smem>>>(logp, tgts, inl, tgl, trans, start, B, T, U);
    finalize_kernel<<<1, 32>>>((float*)d_out, B);
    dummy_kernel<<<1, 32>>>();
    dummy_kernel<<<1, 32>>>();
    dummy_kernel<<<1, 32>>>();
}

// round 8
// speedup vs baseline: 3.5328x; 1.0388x over previous
#include <cuda_runtime.h>
#include <cuda_bf16.h>
#include <math.h>

// LF-MMI loss: CTC numerator (log domain) + dense bigram denominator forward.
// Denominator: linear-domain scaled forward, 2-CTA cluster per batch element.
//   Texp column in registers (64 f32x2 pairs/thread), fma.rn.f32x2 MACs.
//   Alpha loads are C++ longlong2 reads (round-5/6 lesson: bare non-volatile
//   asm loads get CSE'd out of the time loop).
//   Cross-CTA partial exchange: per-thread st.async scalar stores directly
//   into the peer's p_in (no staging, no pre-sync, no tid0 bulk-copy
//   serialization), one mbarrier per buffer (anonymous-tx-safe chain).
// Numerator: log-domain CTC forward.

#define CC 256
#define NEGBIG (-1.0e30f)

__device__ float g_num[512];
__device__ float g_den[512];

// den smem byte offsets (dynamic smem)
#define OFF_MBAR 0       // two 8-byte mbarriers (one per buffer)
#define OFF_ASH  16      // 256 floats
#define OFF_PIN  1040    // 2 x 256 floats (incoming partials, double buffered)
#define OFF_RED  3088    // 8 floats
#define DEN_SMEM 3136

__device__ __forceinline__ float blk_sum_256(float v, float* red) {
    int tid = threadIdx.x;
#pragma unroll
    for (int o = 16; o > 0; o >>= 1) v += __shfl_xor_sync(0xffffffffu, v, o);
    if ((tid & 31) == 0) red[tid >> 5] = v;
    __syncthreads();
    float s = red[0] + red[1] + red[2] + red[3] + red[4] + red[5] + red[6] + red[7];
    __syncthreads();
    return s;
}

__device__ __forceinline__ unsigned long long pack2(float lo, float hi) {
    unsigned long long r;
    asm("mov.b64 %0, {%1, %2};" : "=l"(r) : "r"(__float_as_uint(lo)), "r"(__float_as_uint(hi)));
    return r;
}

__device__ __forceinline__ void mbar_wait_parity(unsigned int mbar, unsigned int parity) {
    asm volatile(
        "{\n\t"
        ".reg .pred P;\n\t"
        "WL_%=:\n\t"
        "mbarrier.try_wait.parity.acquire.cluster.shared::cta.b64 P, [%0], %1, 0x989680;\n\t"
        "@P bra.uni WD_%=;\n\t"
        "bra.uni WL_%=;\n\t"
        "WD_%=:\n\t"
        "}" :: "r"(mbar), "r"(parity) : "memory");
}

// ---------------------------------------------------------------------------
// Denominator: cluster of 2 CTAs per batch element. 256 threads each.
// CTA half h owns source rows [h*128, h*128+128); thread tid owns column tid.
// ---------------------------------------------------------------------------
__device__ void den_block(unsigned char* smem_raw,
                          const float* __restrict__ logp,
                          const int* __restrict__ in_len_raw,
                          const float* __restrict__ trans,
                          const float* __restrict__ start,
                          int b, int h, int T, int U) {
    int tid = threadIdx.x;

    unsigned int sbase;
    asm("{ .reg .u64 t; cvta.to.shared.u64 t, %1; cvt.u32.u64 %0, t; }"
        : "=r"(sbase) : "l"(smem_raw));
    unsigned int mbar_l = sbase + OFF_MBAR;

    float* a_sh  = (float*)(smem_raw + OFF_ASH);
    float* p_in  = (float*)(smem_raw + OFF_PIN);
    float* red   = (float*)(smem_raw + OFF_RED);

    int peer = h ^ 1;
    unsigned int mbar_p, pin_p;
    asm("mapa.shared::cluster.u32 %0, %1, %2;" : "=r"(mbar_p) : "r"(mbar_l), "r"(peer));
    asm("mapa.shared::cluster.u32 %0, %1, %2;" : "=r"(pin_p) : "r"(sbase + OFF_PIN), "r"(peer));

    if (tid == 0) {
        asm volatile("mbarrier.init.shared.b64 [%0], %1;" :: "r"(mbar_l),     "r"(1) : "memory");
        asm volatile("mbarrier.init.shared.b64 [%0], %1;" :: "r"(mbar_l + 8), "r"(1) : "memory");
    }

    // This thread's T column in registers: 64 f32x2 pairs (rows pair-major).
    unsigned long long Treg[64];
    const float* trow = trans + (size_t)(h * 128) * CC + tid;
#pragma unroll
    for (int rp = 0; rp < 64; rp++) {
        float e0 = __expf(trow[(2 * rp) * CC]);
        float e1 = __expf(trow[(2 * rp + 1) * CC]);
        Treg[rp] = pack2(e0, e1);
    }

    int inlen = in_len_raw[b];
    int lowc = 2 * U + 1;
    if (inlen < lowc) inlen = lowc;
    if (inlen > T)    inlen = T;

    const float* lpb = logp + (size_t)b * T * CC;

    // alpha0 = exp(start + logp[:,0]) normalized (both CTAs compute identically)
    float a0 = __expf(start[tid] + lpb[tid]);
    __syncthreads();
    float s0 = blk_sum_256(a0, red);
    float logZ = logf(s0);
    a_sh[tid] = a0 * (1.0f / s0);
    float lp_reg = lpb[CC + tid];
    __syncthreads();

    // both CTAs: mbars initialized + alpha ready before any cross-CTA store
    asm volatile("barrier.cluster.arrive.aligned;" ::: "memory");
    asm volatile("barrier.cluster.wait.aligned;" ::: "memory");

    // C++ vector view of my row-half of alpha (aliasing visible to compiler;
    // __syncthreads() forces reload every iteration).
    const longlong2* ap2 = (const longlong2*)(a_sh + h * 128);

    for (int t = 1; t < inlen; ++t) {
        int buf = t & 1;
        unsigned int mb_l = mbar_l + (unsigned)buf * 8u;   // my barrier for this buffer
        unsigned int mb_p = mbar_p + (unsigned)buf * 8u;   // peer's barrier for this buffer

        // Arm my barrier early: its arrive + 1024 expected tx bytes. Phase for
        // mbar[buf] reopened when all threads passed the wait at t-2.
        if (tid == 0) {
            asm volatile("mbarrier.arrive.expect_tx.shared.b64 _, [%0], %1;"
                         :: "r"(mb_l), "r"(1024) : "memory");
        }

        unsigned long long acc0 = 0ull, acc1 = 0ull, acc2 = 0ull, acc3 = 0ull;
#pragma unroll
        for (int i = 0; i < 16; i++) {
            longlong2 x = ap2[2 * i];        // floats 8i..8i+3 as two f32-pairs
            longlong2 y = ap2[2 * i + 1];    // floats 8i+4..8i+7
            unsigned long long a01 = (unsigned long long)x.x;
            unsigned long long a23 = (unsigned long long)x.y;
            unsigned long long a45 = (unsigned long long)y.x;
            unsigned long long a67 = (unsigned long long)y.y;
            asm("fma.rn.f32x2 %0, %1, %2, %0;" : "+l"(acc0) : "l"(a01), "l"(Treg[4 * i + 0]));
            asm("fma.rn.f32x2 %0, %1, %2, %0;" : "+l"(acc1) : "l"(a23), "l"(Treg[4 * i + 1]));
            asm("fma.rn.f32x2 %0, %1, %2, %0;" : "+l"(acc2) : "l"(a45), "l"(Treg[4 * i + 2]));
            asm("fma.rn.f32x2 %0, %1, %2, %0;" : "+l"(acc3) : "l"(a67), "l"(Treg[4 * i + 3]));
        }
        asm("add.rn.f32x2 %0, %0, %1;" : "+l"(acc0) : "l"(acc1));
        asm("add.rn.f32x2 %0, %0, %1;" : "+l"(acc2) : "l"(acc3));
        asm("add.rn.f32x2 %0, %0, %1;" : "+l"(acc0) : "l"(acc2));
        unsigned int plo, phi;
        asm("mov.b64 {%0, %1}, %2;" : "=r"(plo), "=r"(phi) : "l"(acc0));
        float partial = __uint_as_float(plo) + __uint_as_float(phi);

        // Fire my partial straight into the peer's p_in[buf][tid]; completion
        // bytes land on the peer's per-buffer mbarrier. No staging, no sync.
        asm volatile("st.async.shared::cluster.mbarrier::complete_tx::bytes.b32"
                     " [%0], %1, [%2];"
                     :: "r"(pin_p + (unsigned)buf * 1024u + (unsigned)tid * 4u),
                        "r"(__float_as_uint(partial)), "r"(mb_p) : "memory");

        // overlap DSMEM flight with exp + next-frame prefetch
        float pv = __expf(lp_reg);
        if (t + 1 < inlen) lp_reg = lpb[(size_t)(t + 1) * CC + tid];

        // mbar[buf] is used at t, t+2, ...: its k-th use has parity k&1, k=(t-1)>>1
        mbar_wait_parity(mb_l, ((unsigned)(t - 1) >> 1) & 1u);
        float an = (partial + p_in[buf * 256 + tid]) * pv;
        a_sh[tid] = an;

        if (((t & 31) == 31) || (t == inlen - 1)) {
            float s = blk_sum_256(an, red);
            a_sh[tid] = an * (1.0f / s);
            logZ += logf(s);
        }
        __syncthreads();
    }
    if (h == 0 && tid == 0) g_den[b] = logZ;

    asm volatile("barrier.cluster.arrive.aligned;" ::: "memory");
    asm volatile("barrier.cluster.wait.aligned;" ::: "memory");
}

// ---------------------------------------------------------------------------
// CTC numerator block (LOG domain): one block per batch element. 256 threads.
// ---------------------------------------------------------------------------
__device__ void ctc_block(unsigned char* smem_raw,
                          const float* __restrict__ logp,
                          const int* __restrict__ targets,
                          const int* __restrict__ in_len_raw,
                          const int* __restrict__ tgt_len_raw,
                          int b, int T, int U) {
    int tid = threadIdx.x;
    int S = 2 * U + 1;

    float* A0  = (float*)smem_raw;          // S+6 (2 leading NEG guards)
    float* A1  = A0 + (S + 6);
    int*   lab = (int*)(A1 + (S + 6));      // S
    int*   skp = lab + S;                   // S
    float* pc  = (float*)(skp + S);         // 256

    const int* tg = targets + (size_t)b * U;
    int tlen = tgt_len_raw[b];
    if (tlen < 1) tlen = 1;
    if (tlen > U) tlen = U;
    int inlen = in_len_raw[b];
    int lowc = 2 * U + 1;
    if (inlen < lowc) inlen = lowc;
    if (inlen > T)    inlen = T;

    for (int s = tid; s < S; s += 256) {
        int l = 0;
        if (s & 1) {
            l = tg[s >> 1];
            if (l < 1) l = 1;
            if (l > CC - 1) l = CC - 1;
        }
        lab[s] = l;
    }
    for (int s = tid; s < S + 6; s += 256) { A0[s] = NEGBIG; A1[s] = NEGBIG; }
    __syncthreads();
    for (int s = tid; s < S; s += 256)
        skp[s] = (s >= 2 && (s & 1) && lab[s] != lab[s - 2]) ? 1 : 0;

    const float* lpb = logp + (size_t)b * T * CC;
    if (tid == 0) {
        A0[2 + 0] = lpb[0];
        A0[2 + 1] = lpb[lab[1]];
    }
    pc[tid] = lpb[CC + tid];
    float lp_reg = lpb[2 * (size_t)CC + tid];
    __syncthreads();

    float* cur = A0;
    float* nxt = A1;
    for (int t = 1; t < inlen; ++t) {
        {
            int s = tid;
            float a  = cur[s + 2];
            float a1 = cur[s + 1];
            float a2 = skp[s] ? cur[s] : NEGBIG;
            float m  = fmaxf(fmaxf(a, a1), a2);
            float v  = __expf(a - m) + __expf(a1 - m) + __expf(a2 - m);
            nxt[s + 2] = m + __logf(v) + pc[lab[s]];
        }
        if (tid < S - 256) {
            int s = tid + 256;
            float a  = cur[s + 2];
            float a1 = cur[s + 1];
            float a2 = skp[s] ? cur[s] : NEGBIG;
            float m  = fmaxf(fmaxf(a, a1), a2);
            float v  = __expf(a - m) + __expf(a1 - m) + __expf(a2 - m);
            nxt[s + 2] = m + __logf(v) + pc[lab[s]];
        }
        __syncthreads();
        if (t + 1 < inlen) {
            pc[tid] = lp_reg;
            if (t + 2 < inlen) lp_reg = lpb[(size_t)(t + 2) * CC + tid];
        }
        __syncthreads();
        float* tmp = cur; cur = nxt; nxt = tmp;
    }
    if (tid == 0) {
        int last = 2 * tlen;
        float a  = cur[last + 2];
        float a1 = cur[last + 1];
        float m  = fmaxf(a, a1);
        g_num[b] = m + logf(expf(a - m) + expf(a1 - m));
    }
}

__global__ __launch_bounds__(256, 1) __cluster_dims__(2, 1, 1)
void lfmmi_kernel(const float* __restrict__ logp,
                  const int* __restrict__ targets,
                  const int* __restrict__ in_len_raw,
                  const int* __restrict__ tgt_len_raw,
                  const float* __restrict__ trans,
                  const float* __restrict__ start,
                  int B, int T, int U) {
    extern __shared__ unsigned char smem_raw[];
    int blk = blockIdx.x;
    if (blk < 2 * B) {
        den_block(smem_raw, logp, in_len_raw, trans, start, blk >> 1, blk & 1, T, U);
    } else if (blk < 3 * B) {
        ctc_block(smem_raw, logp, targets, in_len_raw, tgt_len_raw, blk - 2 * B, T, U);
    }
}

__global__ void finalize_kernel(float* out, int B) {
    int tid = threadIdx.x;
    float tot = 0.f;
    int cnt = 0;
    for (int b = tid; b < B; b += 32) {
        float v = g_num[b] - g_den[b];
        if (v > 0.5f * NEGBIG) { tot += v; cnt++; }
    }
#pragma unroll
    for (int o = 16; o > 0; o >>= 1) {
        tot += __shfl_xor_sync(0xffffffffu, tot, o);
        cnt += __shfl_xor_sync(0xffffffffu, cnt, o);
    }
    if (tid == 0) {
        int n = (cnt > 0) ? cnt : 1;
        out[0] = -tot / (float)n;
    }
}

// pad launches so ncu (-s 5 -c 1) lands on lfmmi_kernel: 5 launches per call
__global__ void dummy_kernel() {}

extern "C" void kernel_launch(void* const* d_in, const int* in_sizes, int n_in,
                              void* d_out, int out_size) {
    const float* logp   = (const float*)d_in[0];
    const int*   tgts   = (const int*)d_in[1];
    const int*   inl    = (const int*)d_in[2];
    const int*   tgl    = (const int*)d_in[3];
    const float* trans  = (const float*)d_in[4];
    const float* start  = (const float*)d_in[5];

    int B = in_sizes[2];
    int C = in_sizes[5];            // expected 256
    int U = in_sizes[1] / B;
    int T = in_sizes[0] / (B * C);
    int S = 2 * U + 1;

    size_t ctc_smem = (size_t)(2 * (S + 6) + 2 * S + 256 + 16) * 4;
    size_t smem = ctc_smem > DEN_SMEM ? ctc_smem : DEN_SMEM;

    int grid = 3 * B;
    if (grid & 1) grid++;           // cluster size 2 divisibility

    lfmmi_kernel<<<grid, 256, smem>>>(logp, tgts, inl, tgl, trans, start, B, T, U);
    finalize_kernel<<<1, 32>>>((float*)d_out, B);
    dummy_kernel<<<1, 32>>>();
    dummy_kernel<<<1, 32>>>();
    dummy_kernel<<<1, 32>>>();
}

// round 9
// speedup vs baseline: 3.9086x; 1.1064x over previous
#include <cuda_runtime.h>
#include <cuda_bf16.h>
#include <math.h>

// LF-MMI loss: CTC numerator (log domain) + dense bigram denominator forward.
// Denominator: linear-domain scaled forward, 2-CTA cluster per batch element,
//   COLUMN-split: CTA h owns output columns [h*128,(h+1)*128). Warp-group g0
//   (tid<128) accumulates the 128 rows driven by the locally-owned alpha half
//   (starts immediately); g1 (tid>=128) accumulates rows driven by the peer
//   alpha half and absorbs the DSMEM wait -> round trip hides under g0 FMA.
//   Texp column slice in registers (64 f32x2 pairs/thread), fma.rn.f32x2.
//   Exchange: per-thread st.async of the new alpha half, per-buffer mbarriers.
//   Renorm every 32 steps with scalar sum exchange (fixed CTA0-first order).
// Numerator: log-domain CTC forward.

#define CC 256
#define NEGBIG (-1.0e30f)

__device__ float g_num[512];
__device__ float g_den[512];

// den smem byte offsets (dynamic smem)
#define OFF_MBAR   0     // 2 x 8B alpha mbarriers (one per buffer)
#define OFF_SMBAR  16    // 2 x 8B scalar mbarriers (renorm)
#define OFF_SSLOT  32    // 2 x 4B peer half-sum slots (+pad)
#define OFF_ASH    48    // 128 floats: my alpha half
#define OFF_PIN    560   // 2 x 128 floats: peer alpha half (double buffered)
#define OFF_PART   1584  // 2 x 128 floats: g1 partials (double buffered)
#define OFF_RED    2608  // 8 floats
#define OFF_TMP    2640  // 256 floats init scratch
#define DEN_SMEM   3664

__device__ __forceinline__ float blk_sum_256(float v, float* red) {
    int tid = threadIdx.x;
#pragma unroll
    for (int o = 16; o > 0; o >>= 1) v += __shfl_xor_sync(0xffffffffu, v, o);
    if ((tid & 31) == 0) red[tid >> 5] = v;
    __syncthreads();
    float s = red[0] + red[1] + red[2] + red[3] + red[4] + red[5] + red[6] + red[7];
    __syncthreads();
    return s;
}

__device__ __forceinline__ unsigned long long pack2(float lo, float hi) {
    unsigned long long r;
    asm("mov.b64 %0, {%1, %2};" : "=l"(r) : "r"(__float_as_uint(lo)), "r"(__float_as_uint(hi)));
    return r;
}

__device__ __forceinline__ void mbar_wait_parity(unsigned int mbar, unsigned int parity) {
    asm volatile(
        "{\n\t"
        ".reg .pred P;\n\t"
        "WL_%=:\n\t"
        "mbarrier.try_wait.parity.acquire.cluster.shared::cta.b64 P, [%0], %1, 0x989680;\n\t"
        "@P bra.uni WD_%=;\n\t"
        "bra.uni WL_%=;\n\t"
        "WD_%=:\n\t"
        "}" :: "r"(mbar), "r"(parity) : "memory");
}

// ---------------------------------------------------------------------------
// Denominator: cluster of 2 CTAs per batch element. 256 threads each.
// ---------------------------------------------------------------------------
__device__ void den_block(unsigned char* smem_raw,
                          const float* __restrict__ logp,
                          const int* __restrict__ in_len_raw,
                          const float* __restrict__ trans,
                          const float* __restrict__ start,
                          int b, int h, int T, int U) {
    int tid = threadIdx.x;
    int g   = tid >> 7;       // 0: rows of my alpha half; 1: rows of peer half
    int j   = tid & 127;      // column within my half
    int gcol = h * 128 + j;   // global output column

    unsigned int sbase;
    asm("{ .reg .u64 t; cvta.to.shared.u64 t, %1; cvt.u32.u64 %0, t; }"
        : "=r"(sbase) : "l"(smem_raw));
    unsigned int mbar_l  = sbase + OFF_MBAR;
    unsigned int smbar_l = sbase + OFF_SMBAR;

    float* a_sh   = (float*)(smem_raw + OFF_ASH);
    float* p_in   = (float*)(smem_raw + OFF_PIN);
    float* part   = (float*)(smem_raw + OFF_PART);
    float* red    = (float*)(smem_raw + OFF_RED);
    float* tmp    = (float*)(smem_raw + OFF_TMP);
    float* s_slot = (float*)(smem_raw + OFF_SSLOT);

    int peer = h ^ 1;
    unsigned int mbar_p, smbar_p, pin_p, sslot_p;
    asm("mapa.shared::cluster.u32 %0, %1, %2;" : "=r"(mbar_p)  : "r"(mbar_l), "r"(peer));
    asm("mapa.shared::cluster.u32 %0, %1, %2;" : "=r"(smbar_p) : "r"(smbar_l), "r"(peer));
    asm("mapa.shared::cluster.u32 %0, %1, %2;" : "=r"(pin_p)   : "r"(sbase + OFF_PIN), "r"(peer));
    asm("mapa.shared::cluster.u32 %0, %1, %2;" : "=r"(sslot_p) : "r"(sbase + OFF_SSLOT), "r"(peer));

    if (tid == 0) {
        asm volatile("mbarrier.init.shared.b64 [%0], %1;" :: "r"(mbar_l),      "r"(1) : "memory");
        asm volatile("mbarrier.init.shared.b64 [%0], %1;" :: "r"(mbar_l + 8),  "r"(1) : "memory");
        asm volatile("mbarrier.init.shared.b64 [%0], %1;" :: "r"(smbar_l),     "r"(1) : "memory");
        asm volatile("mbarrier.init.shared.b64 [%0], %1;" :: "r"(smbar_l + 8), "r"(1) : "memory");
    }

    // T column slice in registers: rows [(h^g)*128, +128) for column gcol.
    unsigned long long Treg[64];
    const float* trow = trans + (size_t)((h ^ g) * 128) * CC + gcol;
#pragma unroll
    for (int rp = 0; rp < 64; rp++) {
        float e0 = __expf(trow[(2 * rp) * CC]);
        float e1 = __expf(trow[(2 * rp + 1) * CC]);
        Treg[rp] = pack2(e0, e1);
    }

    int inlen = in_len_raw[b];
    int lowc = 2 * U + 1;
    if (inlen < lowc) inlen = lowc;
    if (inlen > T)    inlen = T;

    const float* lpb = logp + (size_t)b * T * CC;

    // alpha0 = exp(start + logp[:,0]) normalized; seed a_sh (my half) and
    // p_in[0] (peer half, computed locally -- no exchange needed for t=1).
    float a0 = __expf(start[tid] + lpb[tid]);
    tmp[tid] = a0;
    __syncthreads();
    float s0 = blk_sum_256(a0, red);
    float logZ = logf(s0);
    float inv0 = 1.0f / s0;
    if (tid < 128) {
        a_sh[tid]        = tmp[h * 128 + tid] * inv0;
        p_in[0 + tid]    = tmp[peer * 128 + tid] * inv0;
    }
    float lp_reg = (g == 0) ? lpb[CC + gcol] : 0.0f;   // frame t=1 for my col
    __syncthreads();

    asm volatile("barrier.cluster.arrive.aligned;" ::: "memory");
    asm volatile("barrier.cluster.wait.aligned;" ::: "memory");

    const longlong2* own2 = (const longlong2*)a_sh;
    int ph0 = 0, ph1 = 0;   // per-buffer phase parity trackers (g1 only uses)
    int rc = 0;             // renorm counter

    for (int t = 1; t < inlen; ++t) {
        int buf = t & 1;
        if (tid == 0) {   // arm for incoming peer alpha(t): 128 floats
            asm volatile("mbarrier.arrive.expect_tx.shared.b64 _, [%0], %1;"
                         :: "r"(mbar_l + (unsigned)buf * 8u), "r"(512) : "memory");
        }

        float partial, pv = 0.0f;
        if (g == 0) {
            // rows fed by my own alpha half: start immediately
            unsigned long long acc0 = 0ull, acc1 = 0ull, acc2 = 0ull, acc3 = 0ull;
#pragma unroll
            for (int i = 0; i < 16; i++) {
                longlong2 x = own2[2 * i];
                longlong2 y = own2[2 * i + 1];
                asm("fma.rn.f32x2 %0, %1, %2, %0;" : "+l"(acc0) : "l"((unsigned long long)x.x), "l"(Treg[4 * i + 0]));
                asm("fma.rn.f32x2 %0, %1, %2, %0;" : "+l"(acc1) : "l"((unsigned long long)x.y), "l"(Treg[4 * i + 1]));
                asm("fma.rn.f32x2 %0, %1, %2, %0;" : "+l"(acc2) : "l"((unsigned long long)y.x), "l"(Treg[4 * i + 2]));
                asm("fma.rn.f32x2 %0, %1, %2, %0;" : "+l"(acc3) : "l"((unsigned long long)y.y), "l"(Treg[4 * i + 3]));
            }
            asm("add.rn.f32x2 %0, %0, %1;" : "+l"(acc0) : "l"(acc1));
            asm("add.rn.f32x2 %0, %0, %1;" : "+l"(acc2) : "l"(acc3));
            asm("add.rn.f32x2 %0, %0, %1;" : "+l"(acc0) : "l"(acc2));
            unsigned int plo, phi;
            asm("mov.b64 {%0, %1}, %2;" : "=r"(plo), "=r"(phi) : "l"(acc0));
            partial = __uint_as_float(plo) + __uint_as_float(phi);
            pv = __expf(lp_reg);
            if (t + 1 < inlen) lp_reg = lpb[(size_t)(t + 1) * CC + gcol];
        } else {
            // rows fed by peer alpha half: absorb the DSMEM wait here
            int br = (t - 1) & 1;
            if (t >= 2) {
                int par = br ? ph1 : ph0;
                mbar_wait_parity(mbar_l + (unsigned)br * 8u, (unsigned)par);
                if (br) ph1 ^= 1; else ph0 ^= 1;
            }
            const longlong2* src2 = (const longlong2*)(p_in + br * 128);
            unsigned long long acc0 = 0ull, acc1 = 0ull, acc2 = 0ull, acc3 = 0ull;
#pragma unroll
            for (int i = 0; i < 16; i++) {
                longlong2 x = src2[2 * i];
                longlong2 y = src2[2 * i + 1];
                asm("fma.rn.f32x2 %0, %1, %2, %0;" : "+l"(acc0) : "l"((unsigned long long)x.x), "l"(Treg[4 * i + 0]));
                asm("fma.rn.f32x2 %0, %1, %2, %0;" : "+l"(acc1) : "l"((unsigned long long)x.y), "l"(Treg[4 * i + 1]));
                asm("fma.rn.f32x2 %0, %1, %2, %0;" : "+l"(acc2) : "l"((unsigned long long)y.x), "l"(Treg[4 * i + 2]));
                asm("fma.rn.f32x2 %0, %1, %2, %0;" : "+l"(acc3) : "l"((unsigned long long)y.y), "l"(Treg[4 * i + 3]));
            }
            asm("add.rn.f32x2 %0, %0, %1;" : "+l"(acc0) : "l"(acc1));
            asm("add.rn.f32x2 %0, %0, %1;" : "+l"(acc2) : "l"(acc3));
            asm("add.rn.f32x2 %0, %0, %1;" : "+l"(acc0) : "l"(acc2));
            unsigned int plo, phi;
            asm("mov.b64 {%0, %1}, %2;" : "=r"(plo), "=r"(phi) : "l"(acc0));
            partial = __uint_as_float(plo) + __uint_as_float(phi);
            part[buf * 128 + j] = partial;
        }
        __syncthreads();   // g1 partials visible; g0 alpha reads complete

        float an = 0.0f;
        if (g == 0) an = (partial + part[buf * 128 + j]) * pv;

        bool renorm = ((t & 31) == 31) || (t == inlen - 1);
        if (renorm) {
            float v = (g == 0) ? an : 0.0f;
            float sl = blk_sum_256(v, red);
            int bs = rc & 1;
            if (tid == 0) {
                asm volatile("mbarrier.arrive.expect_tx.shared.b64 _, [%0], %1;"
                             :: "r"(smbar_l + (unsigned)bs * 8u), "r"(4) : "memory");
                asm volatile("st.async.shared::cluster.mbarrier::complete_tx::bytes.b32"
                             " [%0], %1, [%2];"
                             :: "r"(sslot_p + (unsigned)bs * 4u),
                                "r"(__float_as_uint(sl)),
                                "r"(smbar_p + (unsigned)bs * 8u) : "memory");
            }
            mbar_wait_parity(smbar_l + (unsigned)bs * 8u, (unsigned)((rc >> 1) & 1));
            float sp = s_slot[bs];
            float s  = (h == 0) ? (sl + sp) : (sp + sl);   // fixed order: CTA0 half first
            logZ += logf(s);
            if (g == 0) an *= (1.0f / s);
            rc++;
        }

        if (g == 0) {
            a_sh[j] = an;
            asm volatile("st.async.shared::cluster.mbarrier::complete_tx::bytes.b32"
                         " [%0], %1, [%2];"
                         :: "r"(pin_p + (unsigned)buf * 512u + (unsigned)j * 4u),
                            "r"(__float_as_uint(an)),
                            "r"(mbar_p + (unsigned)buf * 8u) : "memory");
        }
        __syncthreads();   // a_sh writes visible for next step's g0 reads
    }
    if (h == 0 && tid == 0) g_den[b] = logZ;

    asm volatile("barrier.cluster.arrive.aligned;" ::: "memory");
    asm volatile("barrier.cluster.wait.aligned;" ::: "memory");
}

// ---------------------------------------------------------------------------
// CTC numerator block (LOG domain): one block per batch element. 256 threads.
// ---------------------------------------------------------------------------
__device__ void ctc_block(unsigned char* smem_raw,
                          const float* __restrict__ logp,
                          const int* __restrict__ targets,
                          const int* __restrict__ in_len_raw,
                          const int* __restrict__ tgt_len_raw,
                          int b, int T, int U) {
    int tid = threadIdx.x;
    int S = 2 * U + 1;

    float* A0  = (float*)smem_raw;          // S+6 (2 leading NEG guards)
    float* A1  = A0 + (S + 6);
    int*   lab = (int*)(A1 + (S + 6));      // S
    int*   skp = lab + S;                   // S
    float* pc  = (float*)(skp + S);         // 256

    const int* tg = targets + (size_t)b * U;
    int tlen = tgt_len_raw[b];
    if (tlen < 1) tlen = 1;
    if (tlen > U) tlen = U;
    int inlen = in_len_raw[b];
    int lowc = 2 * U + 1;
    if (inlen < lowc) inlen = lowc;
    if (inlen > T)    inlen = T;

    for (int s = tid; s < S; s += 256) {
        int l = 0;
        if (s & 1) {
            l = tg[s >> 1];
            if (l < 1) l = 1;
            if (l > CC - 1) l = CC - 1;
        }
        lab[s] = l;
    }
    for (int s = tid; s < S + 6; s += 256) { A0[s] = NEGBIG; A1[s] = NEGBIG; }
    __syncthreads();
    for (int s = tid; s < S; s += 256)
        skp[s] = (s >= 2 && (s & 1) && lab[s] != lab[s - 2]) ? 1 : 0;

    const float* lpb = logp + (size_t)b * T * CC;
    if (tid == 0) {
        A0[2 + 0] = lpb[0];
        A0[2 + 1] = lpb[lab[1]];
    }
    pc[tid] = lpb[CC + tid];
    float lp_reg = lpb[2 * (size_t)CC + tid];
    __syncthreads();

    float* cur = A0;
    float* nxt = A1;
    for (int t = 1; t < inlen; ++t) {
        {
            int s = tid;
            float a  = cur[s + 2];
            float a1 = cur[s + 1];
            float a2 = skp[s] ? cur[s] : NEGBIG;
            float m  = fmaxf(fmaxf(a, a1), a2);
            float v  = __expf(a - m) + __expf(a1 - m) + __expf(a2 - m);
            nxt[s + 2] = m + __logf(v) + pc[lab[s]];
        }
        if (tid < S - 256) {
            int s = tid + 256;
            float a  = cur[s + 2];
            float a1 = cur[s + 1];
            float a2 = skp[s] ? cur[s] : NEGBIG;
            float m  = fmaxf(fmaxf(a, a1), a2);
            float v  = __expf(a - m) + __expf(a1 - m) + __expf(a2 - m);
            nxt[s + 2] = m + __logf(v) + pc[lab[s]];
        }
        __syncthreads();
        if (t + 1 < inlen) {
            pc[tid] = lp_reg;
            if (t + 2 < inlen) lp_reg = lpb[(size_t)(t + 2) * CC + tid];
        }
        __syncthreads();
        float* tmp = cur; cur = nxt; nxt = tmp;
    }
    if (tid == 0) {
        int last = 2 * tlen;
        float a  = cur[last + 2];
        float a1 = cur[last + 1];
        float m  = fmaxf(a, a1);
        g_num[b] = m + logf(expf(a - m) + expf(a1 - m));
    }
}

__global__ __launch_bounds__(256, 1) __cluster_dims__(2, 1, 1)
void lfmmi_kernel(const float* __restrict__ logp,
                  const int* __restrict__ targets,
                  const int* __restrict__ in_len_raw,
                  const int* __restrict__ tgt_len_raw,
                  const float* __restrict__ trans,
                  const float* __restrict__ start,
                  int B, int T, int U) {
    extern __shared__ unsigned char smem_raw[];
    int blk = blockIdx.x;
    if (blk < 2 * B) {
        den_block(smem_raw, logp, in_len_raw, trans, start, blk >> 1, blk & 1, T, U);
    } else if (blk < 3 * B) {
        ctc_block(smem_raw, logp, targets, in_len_raw, tgt_len_raw, blk - 2 * B, T, U);
    }
}

__global__ void finalize_kernel(float* out, int B) {
    int tid = threadIdx.x;
    float tot = 0.f;
    int cnt = 0;
    for (int b = tid; b < B; b += 32) {
        float v = g_num[b] - g_den[b];
        if (v > 0.5f * NEGBIG) { tot += v; cnt++; }
    }
#pragma unroll
    for (int o = 16; o > 0; o >>= 1) {
        tot += __shfl_xor_sync(0xffffffffu, tot, o);
        cnt += __shfl_xor_sync(0xffffffffu, cnt, o);
    }
    if (tid == 0) {
        int n = (cnt > 0) ? cnt : 1;
        out[0] = -tot / (float)n;
    }
}

// pad launches so ncu (-s 5 -c 1) lands on lfmmi_kernel: 5 launches per call
__global__ void dummy_kernel() {}

extern "C" void kernel_launch(void* const* d_in, const int* in_sizes, int n_in,
                              void* d_out, int out_size) {
    const float* logp   = (const float*)d_in[0];
    const int*   tgts   = (const int*)d_in[1];
    const int*   inl    = (const int*)d_in[2];
    const int*   tgl    = (const int*)d_in[3];
    const float* trans  = (const float*)d_in[4];
    const float* start  = (const float*)d_in[5];

    int B = in_sizes[2];
    int C = in_sizes[5];            // expected 256
    int U = in_sizes[1] / B;
    int T = in_sizes[0] / (B * C);
    int S = 2 * U + 1;

    size_t ctc_smem = (size_t)(2 * (S + 6) + 2 * S + 256 + 16) * 4;
    size_t smem = ctc_smem > DEN_SMEM ? ctc_smem : DEN_SMEM;

    int grid = 3 * B;
    if (grid & 1) grid++;           // cluster size 2 divisibility

    lfmmi_kernel<<<grid, 256, smem>>>(logp, tgts, inl, tgl, trans, start, B, T, U);
    finalize_kernel<<<1, 32>>>((float*)d_out, B);
    dummy_kernel<<<1, 32>>>();
    dummy_kernel<<<1, 32>>>();
    dummy_kernel<<<1, 32>>>();
}

// round 10
// speedup vs baseline: 3.9128x; 1.0011x over previous
#include <cuda_runtime.h>
#include <cuda_bf16.h>
#include <math.h>

// LF-MMI loss: CTC numerator (log domain) + dense bigram denominator forward.
// Denominator: linear-domain scaled forward, 2-CTA cluster per batch element,
//   COLUMN-split: CTA h owns output columns [h*128,(h+1)*128). Warp-group g0
//   (tid<128) accumulates the 128 rows driven by the locally-owned alpha half
//   (starts immediately); g1 (tid>=128) accumulates rows driven by the peer
//   alpha half and absorbs the DSMEM wait -> round trip hides under g0 FMA.
//   Texp column slice in registers (64 f32x2 pairs/thread), fma.rn.f32x2.
//   Exchange: per-thread st.async of the new alpha half, per-buffer mbarriers.
//   Renorm every 32 steps with scalar sum exchange (fixed CTA0-first order).
// Numerator: log-domain CTC forward.

#define CC 256
#define NEGBIG (-1.0e30f)

__device__ float g_num[512];
__device__ float g_den[512];

// den smem byte offsets (dynamic smem)
#define OFF_MBAR   0     // 2 x 8B alpha mbarriers (one per buffer)
#define OFF_SMBAR  16    // 2 x 8B scalar mbarriers (renorm)
#define OFF_SSLOT  32    // 2 x 4B peer half-sum slots (+pad)
#define OFF_ASH    48    // 128 floats: my alpha half
#define OFF_PIN    560   // 2 x 128 floats: peer alpha half (double buffered)
#define OFF_PART   1584  // 2 x 128 floats: g1 partials (double buffered)
#define OFF_RED    2608  // 8 floats
#define OFF_TMP    2640  // 256 floats init scratch
#define DEN_SMEM   3664

__device__ __forceinline__ float blk_sum_256(float v, float* red) {
    int tid = threadIdx.x;
#pragma unroll
    for (int o = 16; o > 0; o >>= 1) v += __shfl_xor_sync(0xffffffffu, v, o);
    if ((tid & 31) == 0) red[tid >> 5] = v;
    __syncthreads();
    float s = red[0] + red[1] + red[2] + red[3] + red[4] + red[5] + red[6] + red[7];
    __syncthreads();
    return s;
}

__device__ __forceinline__ unsigned long long pack2(float lo, float hi) {
    unsigned long long r;
    asm("mov.b64 %0, {%1, %2};" : "=l"(r) : "r"(__float_as_uint(lo)), "r"(__float_as_uint(hi)));
    return r;
}

__device__ __forceinline__ void mbar_wait_parity(unsigned int mbar, unsigned int parity) {
    asm volatile(
        "{\n\t"
        ".reg .pred P;\n\t"
        "WL_%=:\n\t"
        "mbarrier.try_wait.parity.acquire.cluster.shared::cta.b64 P, [%0], %1, 0x989680;\n\t"
        "@P bra.uni WD_%=;\n\t"
        "bra.uni WL_%=;\n\t"
        "WD_%=:\n\t"
        "}" :: "r"(mbar), "r"(parity) : "memory");
}

// ---------------------------------------------------------------------------
// Denominator: cluster of 2 CTAs per batch element. 256 threads each.
// ---------------------------------------------------------------------------
__device__ void den_block(unsigned char* smem_raw,
                          const float* __restrict__ logp,
                          const int* __restrict__ in_len_raw,
                          const float* __restrict__ trans,
                          const float* __restrict__ start,
                          int b, int h, int T, int U) {
    int tid = threadIdx.x;
    int g   = tid >> 7;       // 0: rows of my alpha half; 1: rows of peer half
    int j   = tid & 127;      // column within my half
    int gcol = h * 128 + j;   // global output column

    unsigned int sbase;
    asm("{ .reg .u64 t; cvta.to.shared.u64 t, %1; cvt.u32.u64 %0, t; }"
        : "=r"(sbase) : "l"(smem_raw));
    unsigned int mbar_l  = sbase + OFF_MBAR;
    unsigned int smbar_l = sbase + OFF_SMBAR;

    float* a_sh   = (float*)(smem_raw + OFF_ASH);
    float* p_in   = (float*)(smem_raw + OFF_PIN);
    float* part   = (float*)(smem_raw + OFF_PART);
    float* red    = (float*)(smem_raw + OFF_RED);
    float* tmp    = (float*)(smem_raw + OFF_TMP);
    float* s_slot = (float*)(smem_raw + OFF_SSLOT);

    int peer = h ^ 1;
    unsigned int mbar_p, smbar_p, pin_p, sslot_p;
    asm("mapa.shared::cluster.u32 %0, %1, %2;" : "=r"(mbar_p)  : "r"(mbar_l), "r"(peer));
    asm("mapa.shared::cluster.u32 %0, %1, %2;" : "=r"(smbar_p) : "r"(smbar_l), "r"(peer));
    asm("mapa.shared::cluster.u32 %0, %1, %2;" : "=r"(pin_p)   : "r"(sbase + OFF_PIN), "r"(peer));
    asm("mapa.shared::cluster.u32 %0, %1, %2;" : "=r"(sslot_p) : "r"(sbase + OFF_SSLOT), "r"(peer));

    if (tid == 0) {
        asm volatile("mbarrier.init.shared.b64 [%0], %1;" :: "r"(mbar_l),      "r"(1) : "memory");
        asm volatile("mbarrier.init.shared.b64 [%0], %1;" :: "r"(mbar_l + 8),  "r"(1) : "memory");
        asm volatile("mbarrier.init.shared.b64 [%0], %1;" :: "r"(smbar_l),     "r"(1) : "memory");
        asm volatile("mbarrier.init.shared.b64 [%0], %1;" :: "r"(smbar_l + 8), "r"(1) : "memory");
    }

    // T column slice in registers: rows [(h^g)*128, +128) for column gcol.
    unsigned long long Treg[64];
    const float* trow = trans + (size_t)((h ^ g) * 128) * CC + gcol;
#pragma unroll
    for (int rp = 0; rp < 64; rp++) {
        float e0 = __expf(trow[(2 * rp) * CC]);
        float e1 = __expf(trow[(2 * rp + 1) * CC]);
        Treg[rp] = pack2(e0, e1);
    }

    int inlen = in_len_raw[b];
    int lowc = 2 * U + 1;
    if (inlen < lowc) inlen = lowc;
    if (inlen > T)    inlen = T;

    const float* lpb = logp + (size_t)b * T * CC;

    // alpha0 = exp(start + logp[:,0]) normalized; seed a_sh (my half) and
    // p_in[0] (peer half, computed locally -- no exchange needed for t=1).
    float a0 = __expf(start[tid] + lpb[tid]);
    tmp[tid] = a0;
    __syncthreads();
    float s0 = blk_sum_256(a0, red);
    float logZ = logf(s0);
    float inv0 = 1.0f / s0;
    if (tid < 128) {
        a_sh[tid]        = tmp[h * 128 + tid] * inv0;
        p_in[0 + tid]    = tmp[peer * 128 + tid] * inv0;
    }
    float lp_reg = (g == 0) ? lpb[CC + gcol] : 0.0f;   // frame t=1 for my col
    __syncthreads();

    asm volatile("barrier.cluster.arrive.aligned;" ::: "memory");
    asm volatile("barrier.cluster.wait.aligned;" ::: "memory");

    const longlong2* own2 = (const longlong2*)a_sh;
    int ph0 = 0, ph1 = 0;   // per-buffer phase parity trackers (g1 only uses)
    int rc = 0;             // renorm counter

    for (int t = 1; t < inlen; ++t) {
        int buf = t & 1;
        if (tid == 0) {   // arm for incoming peer alpha(t): 128 floats
            asm volatile("mbarrier.arrive.expect_tx.shared.b64 _, [%0], %1;"
                         :: "r"(mbar_l + (unsigned)buf * 8u), "r"(512) : "memory");
        }

        float partial, pv = 0.0f;
        if (g == 0) {
            // rows fed by my own alpha half: start immediately
            unsigned long long acc0 = 0ull, acc1 = 0ull, acc2 = 0ull, acc3 = 0ull;
#pragma unroll
            for (int i = 0; i < 16; i++) {
                longlong2 x = own2[2 * i];
                longlong2 y = own2[2 * i + 1];
                asm("fma.rn.f32x2 %0, %1, %2, %0;" : "+l"(acc0) : "l"((unsigned long long)x.x), "l"(Treg[4 * i + 0]));
                asm("fma.rn.f32x2 %0, %1, %2, %0;" : "+l"(acc1) : "l"((unsigned long long)x.y), "l"(Treg[4 * i + 1]));
                asm("fma.rn.f32x2 %0, %1, %2, %0;" : "+l"(acc2) : "l"((unsigned long long)y.x), "l"(Treg[4 * i + 2]));
                asm("fma.rn.f32x2 %0, %1, %2, %0;" : "+l"(acc3) : "l"((unsigned long long)y.y), "l"(Treg[4 * i + 3]));
            }
            asm("add.rn.f32x2 %0, %0, %1;" : "+l"(acc0) : "l"(acc1));
            asm("add.rn.f32x2 %0, %0, %1;" : "+l"(acc2) : "l"(acc3));
            asm("add.rn.f32x2 %0, %0, %1;" : "+l"(acc0) : "l"(acc2));
            unsigned int plo, phi;
            asm("mov.b64 {%0, %1}, %2;" : "=r"(plo), "=r"(phi) : "l"(acc0));
            partial = __uint_as_float(plo) + __uint_as_float(phi);
            pv = __expf(lp_reg);
            if (t + 1 < inlen) lp_reg = lpb[(size_t)(t + 1) * CC + gcol];
        } else {
            // rows fed by peer alpha half: absorb the DSMEM wait here
            int br = (t - 1) & 1;
            if (t >= 2) {
                int par = br ? ph1 : ph0;
                mbar_wait_parity(mbar_l + (unsigned)br * 8u, (unsigned)par);
                if (br) ph1 ^= 1; else ph0 ^= 1;
            }
            const longlong2* src2 = (const longlong2*)(p_in + br * 128);
            unsigned long long acc0 = 0ull, acc1 = 0ull, acc2 = 0ull, acc3 = 0ull;
#pragma unroll
            for (int i = 0; i < 16; i++) {
                longlong2 x = src2[2 * i];
                longlong2 y = src2[2 * i + 1];
                asm("fma.rn.f32x2 %0, %1, %2, %0;" : "+l"(acc0) : "l"((unsigned long long)x.x), "l"(Treg[4 * i + 0]));
                asm("fma.rn.f32x2 %0, %1, %2, %0;" : "+l"(acc1) : "l"((unsigned long long)x.y), "l"(Treg[4 * i + 1]));
                asm("fma.rn.f32x2 %0, %1, %2, %0;" : "+l"(acc2) : "l"((unsigned long long)y.x), "l"(Treg[4 * i + 2]));
                asm("fma.rn.f32x2 %0, %1, %2, %0;" : "+l"(acc3) : "l"((unsigned long long)y.y), "l"(Treg[4 * i + 3]));
            }
            asm("add.rn.f32x2 %0, %0, %1;" : "+l"(acc0) : "l"(acc1));
            asm("add.rn.f32x2 %0, %0, %1;" : "+l"(acc2) : "l"(acc3));
            asm("add.rn.f32x2 %0, %0, %1;" : "+l"(acc0) : "l"(acc2));
            unsigned int plo, phi;
            asm("mov.b64 {%0, %1}, %2;" : "=r"(plo), "=r"(phi) : "l"(acc0));
            partial = __uint_as_float(plo) + __uint_as_float(phi);
            part[buf * 128 + j] = partial;
        }
        __syncthreads();   // g1 partials visible; g0 alpha reads complete

        float an = 0.0f;
        if (g == 0) an = (partial + part[buf * 128 + j]) * pv;

        bool renorm = ((t & 31) == 31) || (t == inlen - 1);
        if (renorm) {
            float v = (g == 0) ? an : 0.0f;
            float sl = blk_sum_256(v, red);
            int bs = rc & 1;
            if (tid == 0) {
                asm volatile("mbarrier.arrive.expect_tx.shared.b64 _, [%0], %1;"
                             :: "r"(smbar_l + (unsigned)bs * 8u), "r"(4) : "memory");
                asm volatile("st.async.shared::cluster.mbarrier::complete_tx::bytes.b32"
                             " [%0], %1, [%2];"
                             :: "r"(sslot_p + (unsigned)bs * 4u),
                                "r"(__float_as_uint(sl)),
                                "r"(smbar_p + (unsigned)bs * 8u) : "memory");
            }
            mbar_wait_parity(smbar_l + (unsigned)bs * 8u, (unsigned)((rc >> 1) & 1));
            float sp = s_slot[bs];
            float s  = (h == 0) ? (sl + sp) : (sp + sl);   // fixed order: CTA0 half first
            logZ += logf(s);
            if (g == 0) an *= (1.0f / s);
            rc++;
        }

        if (g == 0) {
            a_sh[j] = an;
            asm volatile("st.async.shared::cluster.mbarrier::complete_tx::bytes.b32"
                         " [%0], %1, [%2];"
                         :: "r"(pin_p + (unsigned)buf * 512u + (unsigned)j * 4u),
                            "r"(__float_as_uint(an)),
                            "r"(mbar_p + (unsigned)buf * 8u) : "memory");
        }
        __syncthreads();   // a_sh writes visible for next step's g0 reads
    }
    if (h == 0 && tid == 0) g_den[b] = logZ;

    asm volatile("barrier.cluster.arrive.aligned;" ::: "memory");
    asm volatile("barrier.cluster.wait.aligned;" ::: "memory");
}

// ---------------------------------------------------------------------------
// CTC numerator block (LOG domain): one block per batch element. 256 threads.
// ---------------------------------------------------------------------------
__device__ void ctc_block(unsigned char* smem_raw,
                          const float* __restrict__ logp,
                          const int* __restrict__ targets,
                          const int* __restrict__ in_len_raw,
                          const int* __restrict__ tgt_len_raw,
                          int b, int T, int U) {
    int tid = threadIdx.x;
    int S = 2 * U + 1;

    float* A0  = (float*)smem_raw;          // S+6 (2 leading NEG guards)
    float* A1  = A0 + (S + 6);
    int*   lab = (int*)(A1 + (S + 6));      // S
    int*   skp = lab + S;                   // S
    float* pc  = (float*)(skp + S);         // 256

    const int* tg = targets + (size_t)b * U;
    int tlen = tgt_len_raw[b];
    if (tlen < 1) tlen = 1;
    if (tlen > U) tlen = U;
    int inlen = in_len_raw[b];
    int lowc = 2 * U + 1;
    if (inlen < lowc) inlen = lowc;
    if (inlen > T)    inlen = T;

    for (int s = tid; s < S; s += 256) {
        int l = 0;
        if (s & 1) {
            l = tg[s >> 1];
            if (l < 1) l = 1;
            if (l > CC - 1) l = CC - 1;
        }
        lab[s] = l;
    }
    for (int s = tid; s < S + 6; s += 256) { A0[s] = NEGBIG; A1[s] = NEGBIG; }
    __syncthreads();
    for (int s = tid; s < S; s += 256)
        skp[s] = (s >= 2 && (s & 1) && lab[s] != lab[s - 2]) ? 1 : 0;

    const float* lpb = logp + (size_t)b * T * CC;
    if (tid == 0) {
        A0[2 + 0] = lpb[0];
        A0[2 + 1] = lpb[lab[1]];
    }
    pc[tid] = lpb[CC + tid];
    float lp_reg = lpb[2 * (size_t)CC + tid];
    __syncthreads();

    float* cur = A0;
    float* nxt = A1;
    for (int t = 1; t < inlen; ++t) {
        {
            int s = tid;
            float a  = cur[s + 2];
            float a1 = cur[s + 1];
            float a2 = skp[s] ? cur[s] : NEGBIG;
            float m  = fmaxf(fmaxf(a, a1), a2);
            float v  = __expf(a - m) + __expf(a1 - m) + __expf(a2 - m);
            nxt[s + 2] = m + __logf(v) + pc[lab[s]];
        }
        if (tid < S - 256) {
            int s = tid + 256;
            float a  = cur[s + 2];
            float a1 = cur[s + 1];
            float a2 = skp[s] ? cur[s] : NEGBIG;
            float m  = fmaxf(fmaxf(a, a1), a2);
            float v  = __expf(a - m) + __expf(a1 - m) + __expf(a2 - m);
            nxt[s + 2] = m + __logf(v) + pc[lab[s]];
        }
        __syncthreads();
        if (t + 1 < inlen) {
            pc[tid] = lp_reg;
            if (t + 2 < inlen) lp_reg = lpb[(size_t)(t + 2) * CC + tid];
        }
        __syncthreads();
        float* tmp = cur; cur = nxt; nxt = tmp;
    }
    if (tid == 0) {
        int last = 2 * tlen;
        float a  = cur[last + 2];
        float a1 = cur[last + 1];
        float m  = fmaxf(a, a1);
        g_num[b] = m + logf(expf(a - m) + expf(a1 - m));
    }
}

__global__ __launch_bounds__(256, 1) __cluster_dims__(2, 1, 1)
void lfmmi_kernel(const float* __restrict__ logp,
                  const int* __restrict__ targets,
                  const int* __restrict__ in_len_raw,
                  const int* __restrict__ tgt_len_raw,
                  const float* __restrict__ trans,
                  const float* __restrict__ start,
                  int B, int T, int U) {
    extern __shared__ unsigned char smem_raw[];
    int blk = blockIdx.x;
    if (blk < 2 * B) {
        den_block(smem_raw, logp, in_len_raw, trans, start, blk >> 1, blk & 1, T, U);
    } else if (blk < 3 * B) {
        ctc_block(smem_raw, logp, targets, in_len_raw, tgt_len_raw, blk - 2 * B, T, U);
    }
}

__global__ void finalize_kernel(float* out, int B) {
    int tid = threadIdx.x;
    float tot = 0.f;
    int cnt = 0;
    for (int b = tid; b < B; b += 32) {
        float v = g_num[b] - g_den[b];
        if (v > 0.5f * NEGBIG) { tot += v; cnt++; }
    }
#pragma unroll
    for (int o = 16; o > 0; o >>= 1) {
        tot += __shfl_xor_sync(0xffffffffu, tot, o);
        cnt += __shfl_xor_sync(0xffffffffu, cnt, o);
    }
    if (tid == 0) {
        int n = (cnt > 0) ? cnt : 1;
        out[0] = -tot / (float)n;
    }
}

// pad launches so ncu (-s 5 -c 1) lands on lfmmi_kernel: 5 launches per call
__global__ void dummy_kernel() {}

extern "C" void kernel_launch(void* const* d_in, const int* in_sizes, int n_in,
                              void* d_out, int out_size) {
    const float* logp   = (const float*)d_in[0];
    const int*   tgts   = (const int*)d_in[1];
    const int*   inl    = (const int*)d_in[2];
    const int*   tgl    = (const int*)d_in[3];
    const float* trans  = (const float*)d_in[4];
    const float* start  = (const float*)d_in[5];

    int B = in_sizes[2];
    int C = in_sizes[5];            // expected 256
    int U = in_sizes[1] / B;
    int T = in_sizes[0] / (B * C);
    int S = 2 * U + 1;

    size_t ctc_smem = (size_t)(2 * (S + 6) + 2 * S + 256 + 16) * 4;
    size_t smem = ctc_smem > DEN_SMEM ? ctc_smem : DEN_SMEM;

    int grid = 3 * B;
    if (grid & 1) grid++;           // cluster size 2 divisibility

    lfmmi_kernel<<<grid, 256, smem>>>(logp, tgts, inl, tgl, trans, start, B, T, U);
    finalize_kernel<<<1, 32>>>((float*)d_out, B);
    dummy_kernel<<<1, 32>>>();
    dummy_kernel<<<1, 32>>>();
    dummy_kernel<<<1, 32>>>();
}

// round 11
// speedup vs baseline: 4.0900x; 1.0453x over previous
#include <cuda_runtime.h>
#include <cuda_bf16.h>
#include <math.h>

// LF-MMI loss: CTC numerator (log domain) + dense bigram denominator forward.
// Denominator: linear-domain scaled forward, 2-CTA cluster per batch element,
//   column-split. g0 (tid<128) computes own-half rows + combines/sends; g1
//   computes peer-half rows, paced ONLY by the alpha mbarrier (no end-of-step
//   barrier for g1). Texp slice in registers, fma.rn.f32x2. Exchange:
//   per-thread st.async, per-buffer mbarriers. Renorm every 32 steps g0-only.
// Numerator: log-domain CTC forward.

#define CC 256
#define NEGBIG (-1.0e30f)

__device__ float g_num[512];
__device__ float g_den[512];

// den smem byte offsets (dynamic smem)
#define OFF_MBAR   0     // 2 x 8B alpha mbarriers (one per buffer)
#define OFF_SMBAR  16    // 2 x 8B scalar mbarriers (renorm)
#define OFF_SSLOT  32    // 2 x 4B peer half-sum slots (+pad)
#define OFF_ASH    48    // 128 floats: my alpha half
#define OFF_PIN    560   // 2 x 128 floats: peer alpha half (double buffered)
#define OFF_PART   1584  // 2 x 128 floats: g1 partials (double buffered)
#define OFF_RED    2608  // 8 floats
#define OFF_TMP    2640  // 256 floats init scratch
#define DEN_SMEM   3664

__device__ __forceinline__ float blk_sum_256(float v, float* red) {
    int tid = threadIdx.x;
#pragma unroll
    for (int o = 16; o > 0; o >>= 1) v += __shfl_xor_sync(0xffffffffu, v, o);
    if ((tid & 31) == 0) red[tid >> 5] = v;
    __syncthreads();
    float s = red[0] + red[1] + red[2] + red[3] + red[4] + red[5] + red[6] + red[7];
    __syncthreads();
    return s;
}

__device__ __forceinline__ unsigned long long pack2(float lo, float hi) {
    unsigned long long r;
    asm("mov.b64 %0, {%1, %2};" : "=l"(r) : "r"(__float_as_uint(lo)), "r"(__float_as_uint(hi)));
    return r;
}

__device__ __forceinline__ void mbar_wait_parity(unsigned int mbar, unsigned int parity) {
    asm volatile(
        "{\n\t"
        ".reg .pred P;\n\t"
        "WL_%=:\n\t"
        "mbarrier.try_wait.parity.acquire.cluster.shared::cta.b64 P, [%0], %1, 0x989680;\n\t"
        "@P bra.uni WD_%=;\n\t"
        "bra.uni WL_%=;\n\t"
        "WD_%=:\n\t"
        "}" :: "r"(mbar), "r"(parity) : "memory");
}

__device__ __forceinline__ void bar_g0() {   // g0-only barrier (128 threads)
    asm volatile("bar.sync 1, 128;" ::: "memory");
}

// ---------------------------------------------------------------------------
// Denominator: cluster of 2 CTAs per batch element. 256 threads each.
// ---------------------------------------------------------------------------
__device__ void den_block(unsigned char* smem_raw,
                          const float* __restrict__ logp,
                          const int* __restrict__ in_len_raw,
                          const float* __restrict__ trans,
                          const float* __restrict__ start,
                          int b, int h, int T, int U) {
    int tid = threadIdx.x;
    int g   = tid >> 7;       // 0: own-half rows + combine/send; 1: peer-half rows
    int j   = tid & 127;      // column within my half
    int gcol = h * 128 + j;   // global output column

    unsigned int sbase;
    asm("{ .reg .u64 t; cvta.to.shared.u64 t, %1; cvt.u32.u64 %0, t; }"
        : "=r"(sbase) : "l"(smem_raw));
    unsigned int mbar_l  = sbase + OFF_MBAR;
    unsigned int smbar_l = sbase + OFF_SMBAR;

    float* a_sh   = (float*)(smem_raw + OFF_ASH);
    float* p_in   = (float*)(smem_raw + OFF_PIN);
    float* part   = (float*)(smem_raw + OFF_PART);
    float* red    = (float*)(smem_raw + OFF_RED);
    float* tmp    = (float*)(smem_raw + OFF_TMP);
    float* s_slot = (float*)(smem_raw + OFF_SSLOT);

    int peer = h ^ 1;
    unsigned int mbar_p, smbar_p, pin_p, sslot_p;
    asm("mapa.shared::cluster.u32 %0, %1, %2;" : "=r"(mbar_p)  : "r"(mbar_l), "r"(peer));
    asm("mapa.shared::cluster.u32 %0, %1, %2;" : "=r"(smbar_p) : "r"(smbar_l), "r"(peer));
    asm("mapa.shared::cluster.u32 %0, %1, %2;" : "=r"(pin_p)   : "r"(sbase + OFF_PIN), "r"(peer));
    asm("mapa.shared::cluster.u32 %0, %1, %2;" : "=r"(sslot_p) : "r"(sbase + OFF_SSLOT), "r"(peer));

    if (tid == 0) {
        asm volatile("mbarrier.init.shared.b64 [%0], %1;" :: "r"(mbar_l),      "r"(1) : "memory");
        asm volatile("mbarrier.init.shared.b64 [%0], %1;" :: "r"(mbar_l + 8),  "r"(1) : "memory");
        asm volatile("mbarrier.init.shared.b64 [%0], %1;" :: "r"(smbar_l),     "r"(1) : "memory");
        asm volatile("mbarrier.init.shared.b64 [%0], %1;" :: "r"(smbar_l + 8), "r"(1) : "memory");
    }

    // T column slice in registers: rows [(h^g)*128, +128) for column gcol.
    unsigned long long Treg[64];
    const float* trow = trans + (size_t)((h ^ g) * 128) * CC + gcol;
#pragma unroll
    for (int rp = 0; rp < 64; rp++) {
        float e0 = __expf(trow[(2 * rp) * CC]);
        float e1 = __expf(trow[(2 * rp + 1) * CC]);
        Treg[rp] = pack2(e0, e1);
    }

    int inlen = in_len_raw[b];
    int lowc = 2 * U + 1;
    if (inlen < lowc) inlen = lowc;
    if (inlen > T)    inlen = T;

    const float* lpb = logp + (size_t)b * T * CC;

    // alpha0 = exp(start + logp[:,0]) normalized; seed a_sh (my half) and
    // p_in[0] (peer half, computed locally -- no exchange needed for t=1).
    float a0 = __expf(start[tid] + lpb[tid]);
    tmp[tid] = a0;
    __syncthreads();
    float s0 = blk_sum_256(a0, red);
    float logZ = logf(s0);
    float inv0 = 1.0f / s0;
    if (tid < 128) {
        a_sh[tid]     = tmp[h * 128 + tid] * inv0;
        p_in[0 + tid] = tmp[peer * 128 + tid] * inv0;
    }
    float lp_reg = (g == 0) ? lpb[CC + gcol] : 0.0f;   // frame t=1 for my col
    __syncthreads();

    asm volatile("barrier.cluster.arrive.aligned;" ::: "memory");
    asm volatile("barrier.cluster.wait.aligned;" ::: "memory");

    const longlong2* own2 = (const longlong2*)a_sh;
    int ph0 = 0, ph1 = 0;   // per-buffer phase parity trackers (g1)
    int rc = 0;             // renorm counter (g0)

    if (g == 0) {
        // ------------------------- g0 loop -------------------------
        for (int t = 1; t < inlen; ++t) {
            int buf = t & 1;
            if (tid == 0) {   // arm for incoming peer alpha(t): 128 floats
                asm volatile("mbarrier.arrive.expect_tx.shared.b64 _, [%0], %1;"
                             :: "r"(mbar_l + (unsigned)buf * 8u), "r"(512) : "memory");
            }
            unsigned long long acc0 = 0ull, acc1 = 0ull, acc2 = 0ull, acc3 = 0ull;
#pragma unroll
            for (int i = 0; i < 16; i++) {
                longlong2 x = own2[2 * i];
                longlong2 y = own2[2 * i + 1];
                asm("fma.rn.f32x2 %0, %1, %2, %0;" : "+l"(acc0) : "l"((unsigned long long)x.x), "l"(Treg[4 * i + 0]));
                asm("fma.rn.f32x2 %0, %1, %2, %0;" : "+l"(acc1) : "l"((unsigned long long)x.y), "l"(Treg[4 * i + 1]));
                asm("fma.rn.f32x2 %0, %1, %2, %0;" : "+l"(acc2) : "l"((unsigned long long)y.x), "l"(Treg[4 * i + 2]));
                asm("fma.rn.f32x2 %0, %1, %2, %0;" : "+l"(acc3) : "l"((unsigned long long)y.y), "l"(Treg[4 * i + 3]));
            }
            asm("add.rn.f32x2 %0, %0, %1;" : "+l"(acc0) : "l"(acc1));
            asm("add.rn.f32x2 %0, %0, %1;" : "+l"(acc2) : "l"(acc3));
            asm("add.rn.f32x2 %0, %0, %1;" : "+l"(acc0) : "l"(acc2));
            unsigned int plo, phi;
            asm("mov.b64 {%0, %1}, %2;" : "=r"(plo), "=r"(phi) : "l"(acc0));
            float partial = __uint_as_float(plo) + __uint_as_float(phi);

            float pv = __expf(lp_reg);
            if (t + 1 < inlen) lp_reg = lpb[(size_t)(t + 1) * CC + gcol];

            __syncthreads();   // bar0: g1's part[buf] ready
            float an = (partial + part[buf * 128 + j]) * pv;

            if (((t & 31) == 31) || (t == inlen - 1)) {
                // g0-only renorm
                float v = an;
#pragma unroll
                for (int o = 16; o > 0; o >>= 1) v += __shfl_xor_sync(0xffffffffu, v, o);
                if ((tid & 31) == 0) red[tid >> 5] = v;
                bar_g0();
                float sl = red[0] + red[1] + red[2] + red[3];
                int bs = rc & 1;
                if (tid == 0) {
                    asm volatile("mbarrier.arrive.expect_tx.shared.b64 _, [%0], %1;"
                                 :: "r"(smbar_l + (unsigned)bs * 8u), "r"(4) : "memory");
                    asm volatile("st.async.shared::cluster.mbarrier::complete_tx::bytes.b32"
                                 " [%0], %1, [%2];"
                                 :: "r"(sslot_p + (unsigned)bs * 4u),
                                    "r"(__float_as_uint(sl)),
                                    "r"(smbar_p + (unsigned)bs * 8u) : "memory");
                }
                mbar_wait_parity(smbar_l + (unsigned)bs * 8u, (unsigned)((rc >> 1) & 1));
                float sp = s_slot[bs];
                float s  = (h == 0) ? (sl + sp) : (sp + sl);
                logZ += logf(s);
                an *= (1.0f / s);
                rc++;
                bar_g0();   // protect red reuse
            }

            a_sh[j] = an;
            asm volatile("st.async.shared::cluster.mbarrier::complete_tx::bytes.b32"
                         " [%0], %1, [%2];"
                         :: "r"(pin_p + (unsigned)buf * 512u + (unsigned)j * 4u),
                            "r"(__float_as_uint(an)),
                            "r"(mbar_p + (unsigned)buf * 8u) : "memory");
            bar_g0();          // a_sh WAR before next phase A (g0-only)
        }
        if (h == 0 && tid == 0) g_den[b] = logZ;
    } else {
        // ------------------------- g1 loop -------------------------
        for (int t = 1; t < inlen; ++t) {
            int buf = t & 1;
            int br  = (t - 1) & 1;
            if (t >= 2) {
                int par = br ? ph1 : ph0;
                mbar_wait_parity(mbar_l + (unsigned)br * 8u, (unsigned)par);
                if (br) ph1 ^= 1; else ph0 ^= 1;
            }
            const longlong2* src2 = (const longlong2*)(p_in + br * 128);
            unsigned long long acc0 = 0ull, acc1 = 0ull, acc2 = 0ull, acc3 = 0ull;
#pragma unroll
            for (int i = 0; i < 16; i++) {
                longlong2 x = src2[2 * i];
                longlong2 y = src2[2 * i + 1];
                asm("fma.rn.f32x2 %0, %1, %2, %0;" : "+l"(acc0) : "l"((unsigned long long)x.x), "l"(Treg[4 * i + 0]));
                asm("fma.rn.f32x2 %0, %1, %2, %0;" : "+l"(acc1) : "l"((unsigned long long)x.y), "l"(Treg[4 * i + 1]));
                asm("fma.rn.f32x2 %0, %1, %2, %0;" : "+l"(acc2) : "l"((unsigned long long)y.x), "l"(Treg[4 * i + 2]));
                asm("fma.rn.f32x2 %0, %1, %2, %0;" : "+l"(acc3) : "l"((unsigned long long)y.y), "l"(Treg[4 * i + 3]));
            }
            asm("add.rn.f32x2 %0, %0, %1;" : "+l"(acc0) : "l"(acc1));
            asm("add.rn.f32x2 %0, %0, %1;" : "+l"(acc2) : "l"(acc3));
            asm("add.rn.f32x2 %0, %0, %1;" : "+l"(acc0) : "l"(acc2));
            unsigned int plo, phi;
            asm("mov.b64 {%0, %1}, %2;" : "=r"(plo), "=r"(phi) : "l"(acc0));
            part[buf * 128 + j] = __uint_as_float(plo) + __uint_as_float(phi);

            __syncthreads();   // bar0: hand part[buf] to g0 (g1 never blocks after)
        }
    }

    asm volatile("barrier.cluster.arrive.aligned;" ::: "memory");
    asm volatile("barrier.cluster.wait.aligned;" ::: "memory");
}

// ---------------------------------------------------------------------------
// CTC numerator block (LOG domain): one block per batch element. 256 threads.
// ---------------------------------------------------------------------------
__device__ void ctc_block(unsigned char* smem_raw,
                          const float* __restrict__ logp,
                          const int* __restrict__ targets,
                          const int* __restrict__ in_len_raw,
                          const int* __restrict__ tgt_len_raw,
                          int b, int T, int U) {
    int tid = threadIdx.x;
    int S = 2 * U + 1;

    float* A0  = (float*)smem_raw;          // S+6 (2 leading NEG guards)
    float* A1  = A0 + (S + 6);
    int*   lab = (int*)(A1 + (S + 6));      // S
    int*   skp = lab + S;                   // S
    float* pc  = (float*)(skp + S);         // 256

    const int* tg = targets + (size_t)b * U;
    int tlen = tgt_len_raw[b];
    if (tlen < 1) tlen = 1;
    if (tlen > U) tlen = U;
    int inlen = in_len_raw[b];
    int lowc = 2 * U + 1;
    if (inlen < lowc) inlen = lowc;
    if (inlen > T)    inlen = T;

    for (int s = tid; s < S; s += 256) {
        int l = 0;
        if (s & 1) {
            l = tg[s >> 1];
            if (l < 1) l = 1;
            if (l > CC - 1) l = CC - 1;
        }
        lab[s] = l;
    }
    for (int s = tid; s < S + 6; s += 256) { A0[s] = NEGBIG; A1[s] = NEGBIG; }
    __syncthreads();
    for (int s = tid; s < S; s += 256)
        skp[s] = (s >= 2 && (s & 1) && lab[s] != lab[s - 2]) ? 1 : 0;

    const float* lpb = logp + (size_t)b * T * CC;
    if (tid == 0) {
        A0[2 + 0] = lpb[0];
        A0[2 + 1] = lpb[lab[1]];
    }
    pc[tid] = lpb[CC + tid];
    float lp_reg = lpb[2 * (size_t)CC + tid];
    __syncthreads();

    float* cur = A0;
    float* nxt = A1;
    for (int t = 1; t < inlen; ++t) {
        {
            int s = tid;
            float a  = cur[s + 2];
            float a1 = cur[s + 1];
            float a2 = skp[s] ? cur[s] : NEGBIG;
            float m  = fmaxf(fmaxf(a, a1), a2);
            float v  = __expf(a - m) + __expf(a1 - m) + __expf(a2 - m);
            nxt[s + 2] = m + __logf(v) + pc[lab[s]];
        }
        if (tid < S - 256) {
            int s = tid + 256;
            float a  = cur[s + 2];
            float a1 = cur[s + 1];
            float a2 = skp[s] ? cur[s] : NEGBIG;
            float m  = fmaxf(fmaxf(a, a1), a2);
            float v  = __expf(a - m) + __expf(a1 - m) + __expf(a2 - m);
            nxt[s + 2] = m + __logf(v) + pc[lab[s]];
        }
        __syncthreads();
        if (t + 1 < inlen) {
            pc[tid] = lp_reg;
            if (t + 2 < inlen) lp_reg = lpb[(size_t)(t + 2) * CC + tid];
        }
        __syncthreads();
        float* tmp = cur; cur = nxt; nxt = tmp;
    }
    if (tid == 0) {
        int last = 2 * tlen;
        float a  = cur[last + 2];
        float a1 = cur[last + 1];
        float m  = fmaxf(a, a1);
        g_num[b] = m + logf(expf(a - m) + expf(a1 - m));
    }
}

__global__ __launch_bounds__(256, 1) __cluster_dims__(2, 1, 1)
void lfmmi_kernel(const float* __restrict__ logp,
                  const int* __restrict__ targets,
                  const int* __restrict__ in_len_raw,
                  const int* __restrict__ tgt_len_raw,
                  const float* __restrict__ trans,
                  const float* __restrict__ start,
                  int B, int T, int U) {
    extern __shared__ unsigned char smem_raw[];
    int blk = blockIdx.x;
    if (blk < 2 * B) {
        den_block(smem_raw, logp, in_len_raw, trans, start, blk >> 1, blk & 1, T, U);
    } else if (blk < 3 * B) {
        ctc_block(smem_raw, logp, targets, in_len_raw, tgt_len_raw, blk - 2 * B, T, U);
    }
}

__global__ void finalize_kernel(float* out, int B) {
    int tid = threadIdx.x;
    float tot = 0.f;
    int cnt = 0;
    for (int b = tid; b < B; b += 32) {
        float v = g_num[b] - g_den[b];
        if (v > 0.5f * NEGBIG) { tot += v; cnt++; }
    }
#pragma unroll
    for (int o = 16; o > 0; o >>= 1) {
        tot += __shfl_xor_sync(0xffffffffu, tot, o);
        cnt += __shfl_xor_sync(0xffffffffu, cnt, o);
    }
    if (tid == 0) {
        int n = (cnt > 0) ? cnt : 1;
        out[0] = -tot / (float)n;
    }
}

extern "C" void kernel_launch(void* const* d_in, const int* in_sizes, int n_in,
                              void* d_out, int out_size) {
    const float* logp   = (const float*)d_in[0];
    const int*   tgts   = (const int*)d_in[1];
    const int*   inl    = (const int*)d_in[2];
    const int*   tgl    = (const int*)d_in[3];
    const float* trans  = (const float*)d_in[4];
    const float* start  = (const float*)d_in[5];

    int B = in_sizes[2];
    int C = in_sizes[5];            // expected 256
    int U = in_sizes[1] / B;
    int T = in_sizes[0] / (B * C);
    int S = 2 * U + 1;

    size_t ctc_smem = (size_t)(2 * (S + 6) + 2 * S + 256 + 16) * 4;
    size_t smem = ctc_smem > DEN_SMEM ? ctc_smem : DEN_SMEM;

    int grid = 3 * B;
    if (grid & 1) grid++;           // cluster size 2 divisibility

    lfmmi_kernel<<<grid, 256, smem>>>(logp, tgts, inl, tgl, trans, start, B, T, U);
    finalize_kernel<<<1, 32>>>((float*)d_out, B);
}